// round 8
// baseline (speedup 1.0000x reference)
#include <cuda_runtime.h>
#include <cstdint>

// Problem constants (fixed shapes for this problem)
#define TT   128
#define NN   50000
#define EE   1600000
#define CIN  16
#define CH   32
#define COUTC 8
#define FULL 0xFFFFFFFFu

// ---------------- scratch (device globals; no runtime allocation) ----------
__device__ int   g_is64;
__device__ int   g_cnt_src[NN];
__device__ int   g_cnt_dst[NN];
__device__ int   g_cursor[NN];
__device__ int   g_off[NN + 1];
__device__ float g_dinv[NN];
__device__ __align__(16) int2  g_csr[EE];          // {src, w-bits}
__device__ __align__(16) float g_h[NN * CH];
__device__ __align__(16) float g_hR[NN * CH];
__device__ float g_Z[NN * CH];
__device__ float g_AX[(size_t)TT * NN * CIN];      // agg(x_t) for all t

// ---------------- preprocessing (single block) ----------------
__global__ void __launch_bounds__(1024) k_prep(const void* __restrict__ ei, int E) {
    __shared__ int s[1024];
    __shared__ int carry_s;
    int tid = threadIdx.x;

    // ---- dtype detect ----
    long long v = ((const long long*)ei)[tid];
    int bad = (v < 0 || v >= NN) ? 1 : 0;
    int anybad = __syncthreads_or(bad);
    int is64 = anybad ? 0 : 1;
    if (tid == 0) g_is64 = is64;

    // ---- zero h + counters ----
    float4 z4 = make_float4(0.f, 0.f, 0.f, 0.f);
    for (int i = tid; i < NN * CH / 4; i += 1024) ((float4*)g_h)[i] = z4;
    for (int i = tid; i < NN; i += 1024) {
        g_cnt_src[i] = 0; g_cnt_dst[i] = 0; g_cursor[i] = 0;
    }
    __syncthreads();

    // ---- degree count ----
    if (is64) {
        const long long* e64 = (const long long*)ei;
        for (int i = tid; i < E; i += 1024) {
            long long sl = e64[i], dl = e64[(size_t)E + i];
            if (sl >= 0 && sl < NN) atomicAdd(&g_cnt_src[(int)sl], 1);
            if (dl >= 0 && dl < NN) atomicAdd(&g_cnt_dst[(int)dl], 1);
        }
    } else {
        const int* e32 = (const int*)ei;
        for (int i = tid; i < E; i += 1024) {
            int sl = e32[i], dl = e32[E + i];
            if (sl >= 0 && sl < NN) atomicAdd(&g_cnt_src[sl], 1);
            if (dl >= 0 && dl < NN) atomicAdd(&g_cnt_dst[dl], 1);
        }
    }
    __threadfence();
    __syncthreads();

    // ---- dinv ----
    for (int n = tid; n < NN; n += 1024) {
        int dsrc = g_cnt_src[n];
        g_dinv[n] = (dsrc > 0) ? rsqrtf((float)dsrc) : 0.f;
    }
    __syncthreads();

    // ---- exclusive scan of cnt_dst -> g_off ----
    if (tid == 0) carry_s = 0;
    __syncthreads();
    for (int base = 0; base < NN; base += 1024) {
        int i = base + tid;
        int val = (i < NN) ? g_cnt_dst[i] : 0;
        s[tid] = val;
        __syncthreads();
        for (int off = 1; off < 1024; off <<= 1) {
            int x = (tid >= off) ? s[tid - off] : 0;
            __syncthreads();
            s[tid] += x;
            __syncthreads();
        }
        if (i < NN) g_off[i] = carry_s + s[tid] - val;
        __syncthreads();
        if (tid == 0) carry_s += s[1023];
        __syncthreads();
    }
    if (tid == 0) g_off[NN] = carry_s;
}

// launch 1: fill CSR (grid-wide)
__global__ void k_fill(const void* __restrict__ ei, int E) {
    int i = blockIdx.x * blockDim.x + threadIdx.x;
    if (i >= E) return;
    long long sl, dl;
    if (g_is64) {
        sl = ((const long long*)ei)[i];
        dl = ((const long long*)ei)[(size_t)E + i];
    } else {
        sl = ((const int*)ei)[i];
        dl = ((const int*)ei)[E + i];
    }
    if (sl < 0 || sl >= NN || dl < 0 || dl >= NN) return;
    int s = (int)sl, d = (int)dl;
    int pos = g_off[d] + atomicAdd(&g_cursor[d], 1);
    g_csr[pos] = make_int2(s, __float_as_int(-g_dinv[s] * g_dinv[d]));
}

// ---------------- gather helper: warp-uniform int4 CSR reads, MLP=4 -------
__device__ __forceinline__ float gather_h(const float* __restrict__ src, int n, int lane) {
    int i = g_off[n], end = g_off[n + 1];
    float a0 = 0.f, a1 = 0.f, a2 = 0.f, a3 = 0.f;
    if (i < end && (i & 1)) {          // align to int4 boundary
        int2 e = g_csr[i];
        a0 += __int_as_float(e.y) * src[e.x * CH + lane];
        i++;
    }
    for (; i + 4 <= end; i += 4) {
        int4 e01 = *(const int4*)&g_csr[i];
        int4 e23 = *(const int4*)&g_csr[i + 2];
        a0 += __int_as_float(e01.y) * src[e01.x * CH + lane];
        a1 += __int_as_float(e01.w) * src[e01.z * CH + lane];
        a2 += __int_as_float(e23.y) * src[e23.x * CH + lane];
        a3 += __int_as_float(e23.w) * src[e23.z * CH + lane];
    }
    for (; i < end; i++) {
        int2 e = g_csr[i];
        a0 += __int_as_float(e.y) * src[e.x * CH + lane];
    }
    return (a0 + a1) + (a2 + a3);
}

// ---------------- time-parallel precompute: AX[t,n,:] = agg(x_t)[n] -------
__global__ void __launch_bounds__(256, 4) k_ax(const float* __restrict__ X) {
    int warp = threadIdx.x >> 5, lane = threadIdx.x & 31;
    int tp = blockIdx.x / (NN / 8);
    int nb = blockIdx.x % (NN / 8);
    int n  = nb * 8 + warp;
    int t  = tp * 2 + (lane >> 4);
    int ch = lane & 15;
    const float* Xt = X + (size_t)t * NN * CIN;

    int i = g_off[n], end = g_off[n + 1];
    float a0 = 0.f, a1 = 0.f, a2 = 0.f, a3 = 0.f;
    if (i < end && (i & 1)) {
        int2 e = g_csr[i];
        a0 += __int_as_float(e.y) * Xt[e.x * CIN + ch];
        i++;
    }
    for (; i + 4 <= end; i += 4) {
        int4 e01 = *(const int4*)&g_csr[i];
        int4 e23 = *(const int4*)&g_csr[i + 2];
        a0 += __int_as_float(e01.y) * Xt[e01.x * CIN + ch];
        a1 += __int_as_float(e01.w) * Xt[e01.z * CIN + ch];
        a2 += __int_as_float(e23.y) * Xt[e23.x * CIN + ch];
        a3 += __int_as_float(e23.w) * Xt[e23.z * CIN + ch];
    }
    for (; i < end; i++) {
        int2 e = g_csr[i];
        a0 += __int_as_float(e.y) * Xt[e.x * CIN + ch];
    }
    g_AX[((size_t)t * NN + n) * CIN + ch] = (a0 + a1) + (a2 + a3);
}

// ---------------- recurrence kernels ----------------
// 256 thr = 8 warps/block, 5 blocks/SM. Warp handles FOUR nodes.
// Operands staged TRANSPOSED in smem as [channel][node]: the dense loop per
// channel c does 1 weight LDS.128 + 2 broadcast float4 operand loads feeding
// 16 FFMAs, with only ~3 transient float4s live -> low regs + low L1 traffic.

__global__ void __launch_bounds__(256, 5) k_gru_a(
    int t, const float* __restrict__ X,
    const float* __restrict__ Wxz, const float* __restrict__ bxz,
    const float* __restrict__ Whz, const float* __restrict__ bhz,
    const float* __restrict__ Wxr, const float* __restrict__ bxr,
    const float* __restrict__ Whr, const float* __restrict__ bhr)
{
    __shared__ float4 s_wx[CIN * CH];   // {wxz0, wxz1, wxr0, wxr1}[c][j]
    __shared__ float4 s_wh[CH * CH];    // {whz0, whz1, whr0, whr1}[c][j]
    __shared__ float  s_bz[CH], s_br[CH];
    __shared__ __align__(16) float s_h [8][CH * 4];  // [warp][c*4+node]
    __shared__ __align__(16) float s_a [8][CH * 4];
    __shared__ __align__(16) float s_xp[8][CH * 4];  // packed: c<16 x, c>=16 agg(x)
    int tid = threadIdx.x;
    for (int i = tid; i < CIN * CH; i += 256)
        s_wx[i] = make_float4(Wxz[i], Wxz[CIN * CH + i], Wxr[i], Wxr[CIN * CH + i]);
    for (int i = tid; i < CH * CH; i += 256)
        s_wh[i] = make_float4(Whz[i], Whz[CH * CH + i], Whr[i], Whr[CH * CH + i]);
    if (tid < CH) { s_bz[tid] = bxz[tid] + bhz[tid]; s_br[tid] = bxr[tid] + bhr[tid]; }
    __syncthreads();

    const float* Xt  = X + (size_t)t * NN * CIN;
    const float* AXt = g_AX + (size_t)t * NN * CIN;
    int lane = tid & 31, wid = tid >> 5;
    int cx = lane & 15;
    int gw = blockIdx.x * 8 + wid, nw = gridDim.x * 8;
    for (int p = gw; p < NN / 4; p += nw) {
        int n0 = 4 * p;
        float h0 = g_h[(n0 + 0) * CH + lane];
        float h1 = g_h[(n0 + 1) * CH + lane];
        float h2 = g_h[(n0 + 2) * CH + lane];
        float h3 = g_h[(n0 + 3) * CH + lane];
        float xp0, xp1, xp2, xp3;
        if (lane < 16) {
            xp0 = Xt[(n0 + 0) * CIN + cx];  xp1 = Xt[(n0 + 1) * CIN + cx];
            xp2 = Xt[(n0 + 2) * CIN + cx];  xp3 = Xt[(n0 + 3) * CIN + cx];
        } else {
            xp0 = AXt[(n0 + 0) * CIN + cx]; xp1 = AXt[(n0 + 1) * CIN + cx];
            xp2 = AXt[(n0 + 2) * CIN + cx]; xp3 = AXt[(n0 + 3) * CIN + cx];
        }
        float a0 = gather_h(g_h, n0 + 0, lane);
        float a1 = gather_h(g_h, n0 + 1, lane);
        float a2 = gather_h(g_h, n0 + 2, lane);
        float a3 = gather_h(g_h, n0 + 3, lane);

        // stage transposed: one STS.128 each (conflict-free 16B/lane)
        *(float4*)&s_h [wid][lane * 4] = make_float4(h0, h1, h2, h3);
        *(float4*)&s_a [wid][lane * 4] = make_float4(a0, a1, a2, a3);
        *(float4*)&s_xp[wid][lane * 4] = make_float4(xp0, xp1, xp2, xp3);
        __syncwarp();

        float z0 = s_bz[lane], r0 = s_br[lane];
        float z1 = z0, r1 = r0, z2 = z0, r2 = r0, z3 = z0, r3 = r0;

        // x side: per c, 1 weight LDS.128 + 2 broadcast operand quads
#pragma unroll
        for (int c = 0; c < CIN; c++) {
            float4 w  = s_wx[c * CH + lane];
            float4 x4 = *(const float4*)&s_xp[wid][c * 4];
            float4 A4 = *(const float4*)&s_xp[wid][(16 + c) * 4];
            z0 += x4.x * w.x + A4.x * w.y;  r0 += x4.x * w.z + A4.x * w.w;
            z1 += x4.y * w.x + A4.y * w.y;  r1 += x4.y * w.z + A4.y * w.w;
            z2 += x4.z * w.x + A4.z * w.y;  r2 += x4.z * w.z + A4.z * w.w;
            z3 += x4.w * w.x + A4.w * w.y;  r3 += x4.w * w.z + A4.w * w.w;
        }
        // h side
#pragma unroll
        for (int c = 0; c < CH; c++) {
            float4 w  = s_wh[c * CH + lane];
            float4 h4 = *(const float4*)&s_h[wid][c * 4];
            float4 a4 = *(const float4*)&s_a[wid][c * 4];
            z0 += h4.x * w.x + a4.x * w.y;  r0 += h4.x * w.z + a4.x * w.w;
            z1 += h4.y * w.x + a4.y * w.y;  r1 += h4.y * w.z + a4.y * w.w;
            z2 += h4.z * w.x + a4.z * w.y;  r2 += h4.z * w.z + a4.z * w.w;
            z3 += h4.w * w.x + a4.w * w.y;  r3 += h4.w * w.z + a4.w * w.w;
        }
        z0 = 1.f / (1.f + __expf(-z0));  r0 = 1.f / (1.f + __expf(-r0));
        z1 = 1.f / (1.f + __expf(-z1));  r1 = 1.f / (1.f + __expf(-r1));
        z2 = 1.f / (1.f + __expf(-z2));  r2 = 1.f / (1.f + __expf(-r2));
        z3 = 1.f / (1.f + __expf(-z3));  r3 = 1.f / (1.f + __expf(-r3));
        g_Z [(n0 + 0) * CH + lane] = z0;  g_hR[(n0 + 0) * CH + lane] = h0 * r0;
        g_Z [(n0 + 1) * CH + lane] = z1;  g_hR[(n0 + 1) * CH + lane] = h1 * r1;
        g_Z [(n0 + 2) * CH + lane] = z2;  g_hR[(n0 + 2) * CH + lane] = h2 * r2;
        g_Z [(n0 + 3) * CH + lane] = z3;  g_hR[(n0 + 3) * CH + lane] = h3 * r3;
        __syncwarp();
    }
}

__global__ void __launch_bounds__(256, 5) k_gru_b(
    int t, const float* __restrict__ X,
    const float* __restrict__ Wxh, const float* __restrict__ bxh,
    const float* __restrict__ Whh, const float* __restrict__ bhh,
    const float* __restrict__ fcw, const float* __restrict__ fcb,
    float* __restrict__ out)
{
    __shared__ float2 s_wx[CIN * CH];   // {wxh0, wxh1}
    __shared__ float2 s_wh[CH * CH];    // {whh0, whh1}
    __shared__ float  s_fcw[CH * COUTC];
    __shared__ float  s_bh[CH];
    __shared__ float  s_fcb[COUTC];
    __shared__ __align__(16) float s_hr[8][CH * 4];  // [warp][c*4+node]
    __shared__ __align__(16) float s_a [8][CH * 4];
    __shared__ __align__(16) float s_xp[8][CH * 4];
    __shared__ __align__(16) float s_hn[8][CH * 4];
    int tid = threadIdx.x;
    for (int i = tid; i < CIN * CH; i += 256)
        s_wx[i] = make_float2(Wxh[i], Wxh[CIN * CH + i]);
    for (int i = tid; i < CH * CH; i += 256)
        s_wh[i] = make_float2(Whh[i], Whh[CH * CH + i]);
    for (int i = tid; i < CH * COUTC; i += 256) s_fcw[i] = fcw[i];
    if (tid < CH)    s_bh[tid]  = bxh[tid] + bhh[tid];
    if (tid < COUTC) s_fcb[tid] = fcb[tid];
    __syncthreads();

    const float* Xt  = X + (size_t)t * NN * CIN;
    const float* AXt = g_AX + (size_t)t * NN * CIN;
    int lane = tid & 31, wid = tid >> 5;
    int cx = lane & 15;
    int gw = blockIdx.x * 8 + wid, nw = gridDim.x * 8;
    for (int p = gw; p < NN / 4; p += nw) {
        int n0 = 4 * p;
        float h0 = g_h[(n0 + 0) * CH + lane];
        float h1 = g_h[(n0 + 1) * CH + lane];
        float h2 = g_h[(n0 + 2) * CH + lane];
        float h3 = g_h[(n0 + 3) * CH + lane];
        float hr0 = g_hR[(n0 + 0) * CH + lane];
        float hr1 = g_hR[(n0 + 1) * CH + lane];
        float hr2 = g_hR[(n0 + 2) * CH + lane];
        float hr3 = g_hR[(n0 + 3) * CH + lane];
        float zz0 = g_Z[(n0 + 0) * CH + lane];
        float zz1 = g_Z[(n0 + 1) * CH + lane];
        float zz2 = g_Z[(n0 + 2) * CH + lane];
        float zz3 = g_Z[(n0 + 3) * CH + lane];
        float xp0, xp1, xp2, xp3;
        if (lane < 16) {
            xp0 = Xt[(n0 + 0) * CIN + cx];  xp1 = Xt[(n0 + 1) * CIN + cx];
            xp2 = Xt[(n0 + 2) * CIN + cx];  xp3 = Xt[(n0 + 3) * CIN + cx];
        } else {
            xp0 = AXt[(n0 + 0) * CIN + cx]; xp1 = AXt[(n0 + 1) * CIN + cx];
            xp2 = AXt[(n0 + 2) * CIN + cx]; xp3 = AXt[(n0 + 3) * CIN + cx];
        }
        float a0 = gather_h(g_hR, n0 + 0, lane);
        float a1 = gather_h(g_hR, n0 + 1, lane);
        float a2 = gather_h(g_hR, n0 + 2, lane);
        float a3 = gather_h(g_hR, n0 + 3, lane);

        *(float4*)&s_hr[wid][lane * 4] = make_float4(hr0, hr1, hr2, hr3);
        *(float4*)&s_a [wid][lane * 4] = make_float4(a0, a1, a2, a3);
        *(float4*)&s_xp[wid][lane * 4] = make_float4(xp0, xp1, xp2, xp3);
        __syncwarp();

        float c0 = s_bh[lane], c1 = c0, c2 = c0, c3 = c0;
#pragma unroll
        for (int c = 0; c < CIN; c++) {
            float2 w  = s_wx[c * CH + lane];
            float4 x4 = *(const float4*)&s_xp[wid][c * 4];
            float4 A4 = *(const float4*)&s_xp[wid][(16 + c) * 4];
            c0 += x4.x * w.x + A4.x * w.y;
            c1 += x4.y * w.x + A4.y * w.y;
            c2 += x4.z * w.x + A4.z * w.y;
            c3 += x4.w * w.x + A4.w * w.y;
        }
#pragma unroll
        for (int c = 0; c < CH; c++) {
            float2 w  = s_wh[c * CH + lane];
            float4 h4 = *(const float4*)&s_hr[wid][c * 4];
            float4 a4 = *(const float4*)&s_a[wid][c * 4];
            c0 += h4.x * w.x + a4.x * w.y;
            c1 += h4.y * w.x + a4.y * w.y;
            c2 += h4.z * w.x + a4.z * w.y;
            c3 += h4.w * w.x + a4.w * w.y;
        }
        float hn0 = zz0 * h0 + (1.f - zz0) * tanhf(c0);
        float hn1 = zz1 * h1 + (1.f - zz1) * tanhf(c1);
        float hn2 = zz2 * h2 + (1.f - zz2) * tanhf(c2);
        float hn3 = zz3 * h3 + (1.f - zz3) * tanhf(c3);
        g_h[(n0 + 0) * CH + lane] = hn0;
        g_h[(n0 + 1) * CH + lane] = hn1;
        g_h[(n0 + 2) * CH + lane] = hn2;
        g_h[(n0 + 3) * CH + lane] = hn3;

        // out[t, n0..n0+3, :] = hn @ fc_w + fc_b  (one coalesced 128B STG)
        *(float4*)&s_hn[wid][lane * 4] = make_float4(hn0, hn1, hn2, hn3);
        __syncwarp();
        {
            int node = lane >> 3, j = lane & 7;
            float acc = s_fcb[j];
#pragma unroll
            for (int c = 0; c < CH; c++)
                acc += s_hn[wid][c * 4 + node] * s_fcw[c * COUTC + j];
            out[((size_t)t * NN + n0) * COUTC + lane] = acc;
        }
        __syncwarp();
    }
}

// ---------------- launch ----------------
extern "C" void kernel_launch(void* const* d_in, const int* in_sizes, int n_in,
                              void* d_out, int out_size) {
    const float* X   = (const float*)d_in[0];
    const void*  ei  = d_in[1];
    const float* Wxz = (const float*)d_in[2];
    const float* bxz = (const float*)d_in[3];
    const float* Whz = (const float*)d_in[4];
    const float* bhz = (const float*)d_in[5];
    const float* Wxr = (const float*)d_in[6];
    const float* bxr = (const float*)d_in[7];
    const float* Whr = (const float*)d_in[8];
    const float* bhr = (const float*)d_in[9];
    const float* Wxh = (const float*)d_in[10];
    const float* bxh = (const float*)d_in[11];
    const float* Whh = (const float*)d_in[12];
    const float* bhh = (const float*)d_in[13];
    const float* fcw = (const float*)d_in[14];
    const float* fcb = (const float*)d_in[15];
    float* out = (float*)d_out;

    int E = in_sizes[1] / 2;

    // preprocess: prep(0), fill(1), ax(2) -> first k_gru_a is launch idx 3 (ncu)
    k_prep<<<1, 1024>>>(ei, E);
    k_fill<<<(E + 255) / 256, 256>>>(ei, E);
    k_ax<<<(TT / 2) * (NN / 8), 256>>>(X);

    // sequential GRU recurrence
    for (int t = 0; t < TT; t++) {
        k_gru_a<<<740, 256>>>(t, X, Wxz, bxz, Whz, bhz, Wxr, bxr, Whr, bhr);
        k_gru_b<<<740, 256>>>(t, X, Wxh, bxh, Whh, bhh, fcw, fcb, out);
    }
}

// round 9
// speedup vs baseline: 1.1922x; 1.1922x over previous
#include <cuda_runtime.h>
#include <cuda_fp16.h>
#include <cstdint>

// Problem constants (fixed shapes for this problem)
#define TT   128
#define NN   50000
#define EE   1600000
#define CIN  16
#define CH   32
#define COUTC 8
#define FULL 0xFFFFFFFFu

#define GETC(v,u) ((u)==0?(v).x:(u)==1?(v).y:(u)==2?(v).z:(v).w)

// ---------------- scratch (device globals; no runtime allocation) ----------
__device__ int   g_is64;
__device__ int   g_cnt_src[NN];     // zero at load; re-zeroed by k_ax each replay
__device__ int   g_cnt_dst[NN];
__device__ int   g_cursor[NN];
__device__ int   g_off[NN + 1];
__device__ float g_dinv[NN];
__device__ __align__(16) int2   g_csr[EE];          // {src, w-bits}
__device__ __align__(16) float  g_h[NN * CH];
__device__ __align__(16) float  g_hR[NN * CH];
__device__ float  g_Z[NN * CH];
__device__ __align__(16) __half g_h16[NN * CH];     // fp16 gather mirror of h
__device__ __align__(16) __half g_hR16[NN * CH];    // fp16 gather mirror of h*R
__device__ __align__(16) __half g_X16[(size_t)TT * NN * CIN];   // fp16 X
__device__ __align__(16) __half g_AX16[(size_t)TT * NN * CIN];  // fp16 agg(x_t)

// ---------------- launch 0: count + zero + X->fp16 + dtype detect ----------
// Each block detects dtype locally (first 256 int64 words) -> no cross-block race.
__global__ void __launch_bounds__(256) k_count(const void* __restrict__ ei,
                                               const float* __restrict__ X, int E) {
    int tid0 = blockIdx.x * blockDim.x + threadIdx.x;
    int stride = gridDim.x * blockDim.x;

    // local dtype detect: int32 data read as int64 packs two indices -> >= NN
    long long v = ((const long long*)ei)[threadIdx.x];
    int bad = (v < 0 || v >= NN) ? 1 : 0;
    int anybad = __syncthreads_or(bad);
    int is64 = anybad ? 0 : 1;
    if (tid0 == 0) g_is64 = is64;

    // degree count
    if (tid0 < E) {
        long long sl, dl;
        if (is64) {
            sl = ((const long long*)ei)[tid0];
            dl = ((const long long*)ei)[(size_t)E + tid0];
        } else {
            sl = ((const int*)ei)[tid0];
            dl = ((const int*)ei)[E + tid0];
        }
        if (sl >= 0 && sl < NN) atomicAdd(&g_cnt_src[(int)sl], 1);
        if (dl >= 0 && dl < NN) atomicAdd(&g_cnt_dst[(int)dl], 1);
    }

    // zero h + fp16 mirror
    for (int i = tid0; i < NN * CH; i += stride) {
        g_h[i] = 0.f;
        g_h16[i] = __float2half(0.f);
    }

    // convert X -> fp16 (vectorized)
    const size_t XT4 = (size_t)TT * NN * CIN / 4;
    const float4* X4 = (const float4*)X;
    __half2* X16 = (__half2*)g_X16;
    for (size_t i = tid0; i < XT4; i += stride) {
        float4 x = X4[i];
        X16[i * 2]     = __floats2half2_rn(x.x, x.y);
        X16[i * 2 + 1] = __floats2half2_rn(x.z, x.w);
    }
}

// ---------------- launch 1: dinv + exclusive scan (single block) -----------
__global__ void __launch_bounds__(1024) k_scan() {
    __shared__ int s[1024];
    __shared__ int carry_s;
    int tid = threadIdx.x;
    for (int n = tid; n < NN; n += 1024) {
        int dsrc = g_cnt_src[n];
        g_dinv[n] = (dsrc > 0) ? rsqrtf((float)dsrc) : 0.f;
    }
    if (tid == 0) carry_s = 0;
    __syncthreads();
    for (int base = 0; base < NN; base += 1024) {
        int i = base + tid;
        int v = (i < NN) ? g_cnt_dst[i] : 0;
        s[tid] = v;
        __syncthreads();
        for (int off = 1; off < 1024; off <<= 1) {
            int x = (tid >= off) ? s[tid - off] : 0;
            __syncthreads();
            s[tid] += x;
            __syncthreads();
        }
        if (i < NN) g_off[i] = carry_s + s[tid] - v;   // exclusive
        __syncthreads();
        if (tid == 0) carry_s += s[1023];
        __syncthreads();
    }
    if (tid == 0) g_off[NN] = carry_s;
}

// ---------------- launch 2: fill CSR ----------------
__global__ void k_fill(const void* __restrict__ ei, int E) {
    int i = blockIdx.x * blockDim.x + threadIdx.x;
    if (i >= E) return;
    long long sl, dl;
    if (g_is64) {
        sl = ((const long long*)ei)[i];
        dl = ((const long long*)ei)[(size_t)E + i];
    } else {
        sl = ((const int*)ei)[i];
        dl = ((const int*)ei)[E + i];
    }
    if (sl < 0 || sl >= NN || dl < 0 || dl >= NN) return;
    int s = (int)sl, d = (int)dl;
    int pos = g_off[d] + atomicAdd(&g_cursor[d], 1);
    g_csr[pos] = make_int2(s, __float_as_int(-g_dinv[s] * g_dinv[d]));
}

// ---------------- launch 3: AX[t,n,:] = agg(x_t)[n] (fp16 in/out) ----------
// 8 warps/block; warp = node, half-warps = two timesteps, ch = lane&15.
// Also re-zeroes the degree counters so the next graph replay starts clean.
__global__ void __launch_bounds__(256, 4) k_ax() {
    int gi = blockIdx.x * 256 + threadIdx.x;
    if (gi < NN) { g_cnt_src[gi] = 0; g_cnt_dst[gi] = 0; g_cursor[gi] = 0; }

    int warp = threadIdx.x >> 5, lane = threadIdx.x & 31;
    int tp = blockIdx.x / (NN / 8);
    int nb = blockIdx.x % (NN / 8);
    int n  = nb * 8 + warp;
    int t  = tp * 2 + (lane >> 4);
    int ch = lane & 15;
    const __half* Xt = g_X16 + (size_t)t * NN * CIN;

    int i = g_off[n], end = g_off[n + 1];
    float a0 = 0.f, a1 = 0.f, a2 = 0.f, a3 = 0.f;
    for (; i + 4 <= end; i += 4) {
        int2 e0 = g_csr[i], e1 = g_csr[i + 1], e2 = g_csr[i + 2], e3 = g_csr[i + 3];
        a0 += __int_as_float(e0.y) * __half2float(Xt[e0.x * CIN + ch]);
        a1 += __int_as_float(e1.y) * __half2float(Xt[e1.x * CIN + ch]);
        a2 += __int_as_float(e2.y) * __half2float(Xt[e2.x * CIN + ch]);
        a3 += __int_as_float(e3.y) * __half2float(Xt[e3.x * CIN + ch]);
    }
    for (; i < end; i++) {
        int2 e = g_csr[i];
        a0 += __int_as_float(e.y) * __half2float(Xt[e.x * CIN + ch]);
    }
    g_AX16[((size_t)t * NN + n) * CIN + ch] = __float2half((a0 + a1) + (a2 + a3));
}

// ---------------- gather helper: warp-uniform CSR, fp16 source, MLP=4 -----
__device__ __forceinline__ float gather_h16(const __half* __restrict__ src, int n, int lane) {
    int i = g_off[n], end = g_off[n + 1];
    float a0 = 0.f, a1 = 0.f, a2 = 0.f, a3 = 0.f;
    for (; i + 4 <= end; i += 4) {
        int2 e0 = g_csr[i], e1 = g_csr[i + 1], e2 = g_csr[i + 2], e3 = g_csr[i + 3];
        a0 += __int_as_float(e0.y) * __half2float(src[e0.x * CH + lane]);
        a1 += __int_as_float(e1.y) * __half2float(src[e1.x * CH + lane]);
        a2 += __int_as_float(e2.y) * __half2float(src[e2.x * CH + lane]);
        a3 += __int_as_float(e3.y) * __half2float(src[e3.x * CH + lane]);
    }
    for (; i < end; i++) {
        int2 e = g_csr[i];
        a0 += __int_as_float(e.y) * __half2float(src[e.x * CH + lane]);
    }
    return (a0 + a1) + (a2 + a3);
}

// ---------------- recurrence kernels (proven R5 structure) ----------------
// 256 thr = 8 warps/block. Warp handles a node PAIR. Lane = hidden channel.

__global__ void __launch_bounds__(256, 4) k_gru_a(
    int t, const float* __restrict__ X,
    const float* __restrict__ Wxz, const float* __restrict__ bxz,
    const float* __restrict__ Whz, const float* __restrict__ bhz,
    const float* __restrict__ Wxr, const float* __restrict__ bxr,
    const float* __restrict__ Whr, const float* __restrict__ bhr)
{
    __shared__ float4 s_wx[CIN * CH];   // {wxz0, wxz1, wxr0, wxr1}[c][j]
    __shared__ float4 s_wh[CH * CH];    // {whz0, whz1, whr0, whr1}[c][j]
    __shared__ float  s_bz[CH], s_br[CH];
    __shared__ __align__(16) float s_st[8][6][CH];  // [warp][hA,aA,hB,aB,xpA,xpB]
    int tid = threadIdx.x;
    for (int i = tid; i < CIN * CH; i += 256)
        s_wx[i] = make_float4(Wxz[i], Wxz[CIN * CH + i], Wxr[i], Wxr[CIN * CH + i]);
    for (int i = tid; i < CH * CH; i += 256)
        s_wh[i] = make_float4(Whz[i], Whz[CH * CH + i], Whr[i], Whr[CH * CH + i]);
    if (tid < CH) { s_bz[tid] = bxz[tid] + bhz[tid]; s_br[tid] = bxr[tid] + bhr[tid]; }
    __syncthreads();

    const float*  Xt  = X + (size_t)t * NN * CIN;
    const __half* AXt = g_AX16 + (size_t)t * NN * CIN;
    int lane = tid & 31, wid = tid >> 5;
    int cx = lane & 15;
    int gw = blockIdx.x * 8 + wid, nw = gridDim.x * 8;
    for (int p = gw; p < NN / 2; p += nw) {
        int nA = 2 * p, nB = 2 * p + 1;
        float hA = g_h[nA * CH + lane];
        float hB = g_h[nB * CH + lane];
        // packed x vector: [0..15]=x, [16..31]=agg(x)
        float xpA, xpB;
        if (lane < 16) {
            xpA = Xt[nA * CIN + cx];
            xpB = Xt[nB * CIN + cx];
        } else {
            xpA = __half2float(AXt[nA * CIN + cx]);
            xpB = __half2float(AXt[nB * CIN + cx]);
        }
        float aA = gather_h16(g_h16, nA, lane);
        float aB = gather_h16(g_h16, nB, lane);

        s_st[wid][0][lane] = hA;  s_st[wid][1][lane] = aA;
        s_st[wid][2][lane] = hB;  s_st[wid][3][lane] = aB;
        s_st[wid][4][lane] = xpA; s_st[wid][5][lane] = xpB;
        __syncwarp();

        float zA = s_bz[lane], rA = s_br[lane];
        float zB = zA,         rB = rA;

        const float4* hAp = (const float4*)&s_st[wid][0][0];
        const float4* aAp = (const float4*)&s_st[wid][1][0];
        const float4* hBp = (const float4*)&s_st[wid][2][0];
        const float4* aBp = (const float4*)&s_st[wid][3][0];
        const float4* xAp = (const float4*)&s_st[wid][4][0];
        const float4* xBp = (const float4*)&s_st[wid][5][0];

#pragma unroll
        for (int c4 = 0; c4 < 4; c4++) {
            float4 x4A = xAp[c4], ax4A = xAp[4 + c4];
            float4 x4B = xBp[c4], ax4B = xBp[4 + c4];
#pragma unroll
            for (int u = 0; u < 4; u++) {
                float4 w = s_wx[(c4 * 4 + u) * CH + lane];
                float xa = GETC(x4A, u), aa = GETC(ax4A, u);
                float xb = GETC(x4B, u), ab = GETC(ax4B, u);
                zA += xa * w.x + aa * w.y;  rA += xa * w.z + aa * w.w;
                zB += xb * w.x + ab * w.y;  rB += xb * w.z + ab * w.w;
            }
        }
#pragma unroll
        for (int c4 = 0; c4 < 8; c4++) {
            float4 h4A = hAp[c4], a4A = aAp[c4];
            float4 h4B = hBp[c4], a4B = aBp[c4];
#pragma unroll
            for (int u = 0; u < 4; u++) {
                float4 w = s_wh[(c4 * 4 + u) * CH + lane];
                float ha = GETC(h4A, u), aa = GETC(a4A, u);
                float hb = GETC(h4B, u), ab = GETC(a4B, u);
                zA += ha * w.x + aa * w.y;  rA += ha * w.z + aa * w.w;
                zB += hb * w.x + ab * w.y;  rB += hb * w.z + ab * w.w;
            }
        }
        zA = 1.f / (1.f + __expf(-zA));
        rA = 1.f / (1.f + __expf(-rA));
        zB = 1.f / (1.f + __expf(-zB));
        rB = 1.f / (1.f + __expf(-rB));
        float hrA = hA * rA, hrB = hB * rB;
        g_Z  [nA * CH + lane] = zA;  g_hR  [nA * CH + lane] = hrA;
        g_Z  [nB * CH + lane] = zB;  g_hR  [nB * CH + lane] = hrB;
        g_hR16[nA * CH + lane] = __float2half(hrA);
        g_hR16[nB * CH + lane] = __float2half(hrB);
        __syncwarp();
    }
}

__global__ void __launch_bounds__(256, 4) k_gru_b(
    int t, const float* __restrict__ X,
    const float* __restrict__ Wxh, const float* __restrict__ bxh,
    const float* __restrict__ Whh, const float* __restrict__ bhh,
    const float* __restrict__ fcw, const float* __restrict__ fcb,
    float* __restrict__ out)
{
    __shared__ float2 s_wx[CIN * CH];   // {wxh0, wxh1}
    __shared__ float2 s_wh[CH * CH];    // {whh0, whh1}
    __shared__ float  s_fcw[CH * COUTC];
    __shared__ float  s_bh[CH];
    __shared__ float  s_fcb[COUTC];
    __shared__ __align__(16) float s_st[8][8][CH];  // [hrA,aA,hrB,aB,xpA,xpB,hnA,hnB]
    int tid = threadIdx.x;
    for (int i = tid; i < CIN * CH; i += 256)
        s_wx[i] = make_float2(Wxh[i], Wxh[CIN * CH + i]);
    for (int i = tid; i < CH * CH; i += 256)
        s_wh[i] = make_float2(Whh[i], Whh[CH * CH + i]);
    for (int i = tid; i < CH * COUTC; i += 256) s_fcw[i] = fcw[i];
    if (tid < CH)    s_bh[tid]  = bxh[tid] + bhh[tid];
    if (tid < COUTC) s_fcb[tid] = fcb[tid];
    __syncthreads();

    const float*  Xt  = X + (size_t)t * NN * CIN;
    const __half* AXt = g_AX16 + (size_t)t * NN * CIN;
    int lane = tid & 31, wid = tid >> 5;
    int cx = lane & 15;
    int gw = blockIdx.x * 8 + wid, nw = gridDim.x * 8;
    for (int p = gw; p < NN / 2; p += nw) {
        int nA = 2 * p, nB = 2 * p + 1;
        float hA  = g_h [nA * CH + lane];
        float hB  = g_h [nB * CH + lane];
        float hrA = g_hR[nA * CH + lane];
        float hrB = g_hR[nB * CH + lane];
        float zA  = g_Z [nA * CH + lane];
        float zB  = g_Z [nB * CH + lane];
        float xpA, xpB;
        if (lane < 16) {
            xpA = Xt[nA * CIN + cx];
            xpB = Xt[nB * CIN + cx];
        } else {
            xpA = __half2float(AXt[nA * CIN + cx]);
            xpB = __half2float(AXt[nB * CIN + cx]);
        }
        float aA = gather_h16(g_hR16, nA, lane);
        float aB = gather_h16(g_hR16, nB, lane);

        s_st[wid][0][lane] = hrA; s_st[wid][1][lane] = aA;
        s_st[wid][2][lane] = hrB; s_st[wid][3][lane] = aB;
        s_st[wid][4][lane] = xpA; s_st[wid][5][lane] = xpB;
        __syncwarp();

        float cA = s_bh[lane], cB = cA;
        const float4* hAp = (const float4*)&s_st[wid][0][0];
        const float4* aAp = (const float4*)&s_st[wid][1][0];
        const float4* hBp = (const float4*)&s_st[wid][2][0];
        const float4* aBp = (const float4*)&s_st[wid][3][0];
        const float4* xAp = (const float4*)&s_st[wid][4][0];
        const float4* xBp = (const float4*)&s_st[wid][5][0];

#pragma unroll
        for (int c4 = 0; c4 < 4; c4++) {
            float4 x4A = xAp[c4], ax4A = xAp[4 + c4];
            float4 x4B = xBp[c4], ax4B = xBp[4 + c4];
#pragma unroll
            for (int u = 0; u < 4; u++) {
                float2 w = s_wx[(c4 * 4 + u) * CH + lane];
                cA += GETC(x4A, u) * w.x + GETC(ax4A, u) * w.y;
                cB += GETC(x4B, u) * w.x + GETC(ax4B, u) * w.y;
            }
        }
#pragma unroll
        for (int c4 = 0; c4 < 8; c4++) {
            float4 h4A = hAp[c4], a4A = aAp[c4];
            float4 h4B = hBp[c4], a4B = aBp[c4];
#pragma unroll
            for (int u = 0; u < 4; u++) {
                float2 w = s_wh[(c4 * 4 + u) * CH + lane];
                cA += GETC(h4A, u) * w.x + GETC(a4A, u) * w.y;
                cB += GETC(h4B, u) * w.x + GETC(a4B, u) * w.y;
            }
        }
        float hnA = zA * hA + (1.f - zA) * tanhf(cA);
        float hnB = zB * hB + (1.f - zB) * tanhf(cB);
        g_h[nA * CH + lane] = hnA;
        g_h[nB * CH + lane] = hnB;
        g_h16[nA * CH + lane] = __float2half(hnA);
        g_h16[nB * CH + lane] = __float2half(hnB);

        // out = hn @ fc_w + fc_b : lanes 0..7 -> node A, lanes 8..15 -> node B
        s_st[wid][6][lane] = hnA;
        s_st[wid][7][lane] = hnB;
        __syncwarp();
        if (lane < 16) {
            int node = lane >> 3, j = lane & 7;
            const float* hn = &s_st[wid][6 + node][0];
            float acc = s_fcb[j];
#pragma unroll
            for (int c = 0; c < CH; c++) acc += hn[c] * s_fcw[c * COUTC + j];
            int n = node ? nB : nA;
            out[((size_t)t * NN + n) * COUTC + j] = acc;
        }
        __syncwarp();
    }
}

// ---------------- launch ----------------
extern "C" void kernel_launch(void* const* d_in, const int* in_sizes, int n_in,
                              void* d_out, int out_size) {
    const float* X   = (const float*)d_in[0];
    const void*  ei  = d_in[1];
    const float* Wxz = (const float*)d_in[2];
    const float* bxz = (const float*)d_in[3];
    const float* Whz = (const float*)d_in[4];
    const float* bhz = (const float*)d_in[5];
    const float* Wxr = (const float*)d_in[6];
    const float* bxr = (const float*)d_in[7];
    const float* Whr = (const float*)d_in[8];
    const float* bhr = (const float*)d_in[9];
    const float* Wxh = (const float*)d_in[10];
    const float* bxh = (const float*)d_in[11];
    const float* Whh = (const float*)d_in[12];
    const float* bhh = (const float*)d_in[13];
    const float* fcw = (const float*)d_in[14];
    const float* fcb = (const float*)d_in[15];
    float* out = (float*)d_out;

    int E = in_sizes[1] / 2;

    // preprocess: count(0), scan(1), fill(2), ax(3) -> ncu idx3 profiles k_ax
    k_count<<<(E + 255) / 256, 256>>>(ei, X, E);
    k_scan<<<1, 1024>>>();
    k_fill<<<(E + 255) / 256, 256>>>(ei, E);
    k_ax<<<(TT / 2) * (NN / 8), 256>>>();

    // sequential GRU recurrence
    for (int t = 0; t < TT; t++) {
        k_gru_a<<<592, 256>>>(t, X, Wxz, bxz, Whz, bhz, Wxr, bxr, Whr, bhr);
        k_gru_b<<<592, 256>>>(t, X, Wxh, bxh, Whh, bhh, fcw, fcb, out);
    }
}

// round 10
// speedup vs baseline: 1.2250x; 1.0275x over previous
#include <cuda_runtime.h>
#include <cuda_fp16.h>
#include <cstdint>

// Problem constants (fixed shapes for this problem)
#define TT   128
#define NN   50000
#define EE   1600000
#define CIN  16
#define CH   32
#define COUTC 8
#define NB   592          // persistent grid: 148 SMs x 4 blocks (all co-resident)
#define FULL 0xFFFFFFFFu

#define GETC(v,u) ((u)==0?(v).x:(u)==1?(v).y:(u)==2?(v).z:(v).w)

// ---------------- scratch (device globals; no runtime allocation) ----------
__device__ int   g_is64;
__device__ int   g_cnt_src[NN];
__device__ int   g_cnt_dst[NN];
__device__ int   g_cursor[NN];
__device__ int   g_off[NN + 1];
__device__ float g_dinv[NN];
__device__ __align__(16) int2   g_csr[EE];          // {src, w-bits}
__device__ __align__(16) float  g_h[NN * CH];
__device__ __align__(16) float  g_hR[NN * CH];
__device__ float  g_Z[NN * CH];
__device__ __align__(16) __half g_h16[NN * CH];     // fp16 gather mirror of h
__device__ __align__(16) __half g_hR16[NN * CH];    // fp16 gather mirror of h*R
__device__ __align__(16) __half g_X16[(size_t)TT * NN * CIN];   // fp16 X
__device__ __align__(16) __half g_AX16[(size_t)TT * NN * CIN];  // fp16 agg(x_t)

// software grid barrier state (reset each replay by k_count)
__device__ int          g_cnt;
__device__ volatile int g_release;

// fp16 load that bypasses L1 (cross-SM producer/consumer inside one kernel)
__device__ __forceinline__ float ldcg_h(const __half* p) {
    unsigned short v = __ldcg((const unsigned short*)p);
    __half_raw r; r.x = v;
    return __half2float(*(__half*)&r);
}

// ---------------- launch 0: count + zero + X->fp16 + dtype detect ----------
__global__ void __launch_bounds__(256) k_count(const void* __restrict__ ei,
                                               const float* __restrict__ X, int E) {
    int tid0 = blockIdx.x * blockDim.x + threadIdx.x;
    int stride = gridDim.x * blockDim.x;

    long long v = ((const long long*)ei)[threadIdx.x];
    int bad = (v < 0 || v >= NN) ? 1 : 0;
    int anybad = __syncthreads_or(bad);
    int is64 = anybad ? 0 : 1;
    if (tid0 == 0) { g_is64 = is64; g_cnt = 0; g_release = 0; }

    if (tid0 < E) {
        long long sl, dl;
        if (is64) {
            sl = ((const long long*)ei)[tid0];
            dl = ((const long long*)ei)[(size_t)E + tid0];
        } else {
            sl = ((const int*)ei)[tid0];
            dl = ((const int*)ei)[E + tid0];
        }
        if (sl >= 0 && sl < NN) atomicAdd(&g_cnt_src[(int)sl], 1);
        if (dl >= 0 && dl < NN) atomicAdd(&g_cnt_dst[(int)dl], 1);
    }

    for (int i = tid0; i < NN * CH; i += stride) {
        g_h[i] = 0.f;
        g_h16[i] = __float2half(0.f);
    }

    const size_t XT4 = (size_t)TT * NN * CIN / 4;
    const float4* X4 = (const float4*)X;
    __half2* X16 = (__half2*)g_X16;
    for (size_t i = tid0; i < XT4; i += stride) {
        float4 x = X4[i];
        X16[i * 2]     = __floats2half2_rn(x.x, x.y);
        X16[i * 2 + 1] = __floats2half2_rn(x.z, x.w);
    }
}

// ---------------- launch 1: dinv + exclusive scan (single block) -----------
__global__ void __launch_bounds__(1024) k_scan() {
    __shared__ int s[1024];
    __shared__ int carry_s;
    int tid = threadIdx.x;
    for (int n = tid; n < NN; n += 1024) {
        int dsrc = g_cnt_src[n];
        g_dinv[n] = (dsrc > 0) ? rsqrtf((float)dsrc) : 0.f;
    }
    if (tid == 0) carry_s = 0;
    __syncthreads();
    for (int base = 0; base < NN; base += 1024) {
        int i = base + tid;
        int v = (i < NN) ? g_cnt_dst[i] : 0;
        s[tid] = v;
        __syncthreads();
        for (int off = 1; off < 1024; off <<= 1) {
            int x = (tid >= off) ? s[tid - off] : 0;
            __syncthreads();
            s[tid] += x;
            __syncthreads();
        }
        if (i < NN) g_off[i] = carry_s + s[tid] - v;
        __syncthreads();
        if (tid == 0) carry_s += s[1023];
        __syncthreads();
    }
    if (tid == 0) g_off[NN] = carry_s;
}

// ---------------- launch 2: fill CSR ----------------
__global__ void k_fill(const void* __restrict__ ei, int E) {
    int i = blockIdx.x * blockDim.x + threadIdx.x;
    if (i >= E) return;
    long long sl, dl;
    if (g_is64) {
        sl = ((const long long*)ei)[i];
        dl = ((const long long*)ei)[(size_t)E + i];
    } else {
        sl = ((const int*)ei)[i];
        dl = ((const int*)ei)[E + i];
    }
    if (sl < 0 || sl >= NN || dl < 0 || dl >= NN) return;
    int s = (int)sl, d = (int)dl;
    int pos = g_off[d] + atomicAdd(&g_cursor[d], 1);
    g_csr[pos] = make_int2(s, __float_as_int(-g_dinv[s] * g_dinv[d]));
}

// ---------------- launch 3: AX precompute + counter re-zero ----------------
__global__ void __launch_bounds__(256, 4) k_ax() {
    int gi = blockIdx.x * 256 + threadIdx.x;
    if (gi < NN) { g_cnt_src[gi] = 0; g_cnt_dst[gi] = 0; g_cursor[gi] = 0; }

    int warp = threadIdx.x >> 5, lane = threadIdx.x & 31;
    int tp = blockIdx.x / (NN / 8);
    int nb = blockIdx.x % (NN / 8);
    int n  = nb * 8 + warp;
    int t  = tp * 2 + (lane >> 4);
    int ch = lane & 15;
    const __half* Xt = g_X16 + (size_t)t * NN * CIN;

    int i = g_off[n], end = g_off[n + 1];
    float a0 = 0.f, a1 = 0.f, a2 = 0.f, a3 = 0.f;
    for (; i + 4 <= end; i += 4) {
        int2 e0 = g_csr[i], e1 = g_csr[i + 1], e2 = g_csr[i + 2], e3 = g_csr[i + 3];
        a0 += __int_as_float(e0.y) * __half2float(Xt[e0.x * CIN + ch]);
        a1 += __int_as_float(e1.y) * __half2float(Xt[e1.x * CIN + ch]);
        a2 += __int_as_float(e2.y) * __half2float(Xt[e2.x * CIN + ch]);
        a3 += __int_as_float(e3.y) * __half2float(Xt[e3.x * CIN + ch]);
    }
    for (; i < end; i++) {
        int2 e = g_csr[i];
        a0 += __int_as_float(e.y) * __half2float(Xt[e.x * CIN + ch]);
    }
    g_AX16[((size_t)t * NN + n) * CIN + ch] = __float2half((a0 + a1) + (a2 + a3));
}

// ---------------- gather: warp-uniform CSR, fp16 source via L2, MLP=4 -----
__device__ __forceinline__ float gather_h16(const __half* __restrict__ src, int n, int lane) {
    int i = g_off[n], end = g_off[n + 1];
    float a0 = 0.f, a1 = 0.f, a2 = 0.f, a3 = 0.f;
    for (; i + 4 <= end; i += 4) {
        int2 e0 = g_csr[i], e1 = g_csr[i + 1], e2 = g_csr[i + 2], e3 = g_csr[i + 3];
        a0 += __int_as_float(e0.y) * ldcg_h(&src[e0.x * CH + lane]);
        a1 += __int_as_float(e1.y) * ldcg_h(&src[e1.x * CH + lane]);
        a2 += __int_as_float(e2.y) * ldcg_h(&src[e2.x * CH + lane]);
        a3 += __int_as_float(e3.y) * ldcg_h(&src[e3.x * CH + lane]);
    }
    for (; i < end; i++) {
        int2 e = g_csr[i];
        a0 += __int_as_float(e.y) * ldcg_h(&src[e.x * CH + lane]);
    }
    return (a0 + a1) + (a2 + a3);
}

// ---------------- persistent recurrence kernel ----------------
// 592 blocks x 256 thr, all co-resident. Software grid barrier between the
// two phases of each step. Weights loaded to smem ONCE for all 128 steps.
__global__ void __launch_bounds__(256, 4) k_gru(
    const float* __restrict__ X,
    const float* __restrict__ Wxz, const float* __restrict__ bxz,
    const float* __restrict__ Whz, const float* __restrict__ bhz,
    const float* __restrict__ Wxr, const float* __restrict__ bxr,
    const float* __restrict__ Whr, const float* __restrict__ bhr,
    const float* __restrict__ Wxh, const float* __restrict__ bxh,
    const float* __restrict__ Whh, const float* __restrict__ bhh,
    const float* __restrict__ fcw, const float* __restrict__ fcb,
    float* __restrict__ out)
{
    __shared__ float4 s_wx4[CIN * CH];  // {wxz0,wxz1,wxr0,wxr1}   8KB
    __shared__ float4 s_wh4[CH * CH];   // {whz0,whz1,whr0,whr1}  16KB
    __shared__ float2 s_wx2[CIN * CH];  // {wxh0,wxh1}             4KB
    __shared__ float2 s_wh2[CH * CH];   // {whh0,whh1}             8KB
    __shared__ float  s_fcw[CH * COUTC];
    __shared__ float  s_bz[CH], s_br[CH], s_bh[CH], s_fcb[COUTC];
    __shared__ __align__(16) float s_st[8][8][CH];               //  8KB
    int tid = threadIdx.x;
    for (int i = tid; i < CIN * CH; i += 256) {
        s_wx4[i] = make_float4(Wxz[i], Wxz[CIN * CH + i], Wxr[i], Wxr[CIN * CH + i]);
        s_wx2[i] = make_float2(Wxh[i], Wxh[CIN * CH + i]);
    }
    for (int i = tid; i < CH * CH; i += 256) {
        s_wh4[i] = make_float4(Whz[i], Whz[CH * CH + i], Whr[i], Whr[CH * CH + i]);
        s_wh2[i] = make_float2(Whh[i], Whh[CH * CH + i]);
    }
    for (int i = tid; i < CH * COUTC; i += 256) s_fcw[i] = fcw[i];
    if (tid < CH) {
        s_bz[tid] = bxz[tid] + bhz[tid];
        s_br[tid] = bxr[tid] + bhr[tid];
        s_bh[tid] = bxh[tid] + bhh[tid];
    }
    if (tid < COUTC) s_fcb[tid] = fcb[tid];
    __syncthreads();

    int lane = tid & 31, wid = tid >> 5;
    int cx = lane & 15;
    int gw = blockIdx.x * 8 + wid;        // global warp id, 0..4735
    const int nwarp = NB * 8;

    int gen = 0;
    for (int t = 0; t < TT; t++) {
        const float*  Xt  = X + (size_t)t * NN * CIN;
        const __half* AXt = g_AX16 + (size_t)t * NN * CIN;

        // ---------------- phase A: z, r, h*R ----------------
        for (int p = gw; p < NN / 2; p += nwarp) {
            int nA = 2 * p, nB_ = 2 * p + 1;
            float hA = g_h[nA * CH + lane];
            float hB = g_h[nB_ * CH + lane];
            float xpA, xpB;
            if (lane < 16) {
                xpA = Xt[nA * CIN + cx];
                xpB = Xt[nB_ * CIN + cx];
            } else {
                xpA = __half2float(AXt[nA * CIN + cx]);
                xpB = __half2float(AXt[nB_ * CIN + cx]);
            }
            float aA = gather_h16(g_h16, nA, lane);
            float aB = gather_h16(g_h16, nB_, lane);

            s_st[wid][0][lane] = hA;  s_st[wid][1][lane] = aA;
            s_st[wid][2][lane] = hB;  s_st[wid][3][lane] = aB;
            s_st[wid][4][lane] = xpA; s_st[wid][5][lane] = xpB;
            __syncwarp();

            float zA = s_bz[lane], rA = s_br[lane];
            float zB = zA,         rB = rA;
            const float4* hAp = (const float4*)&s_st[wid][0][0];
            const float4* aAp = (const float4*)&s_st[wid][1][0];
            const float4* hBp = (const float4*)&s_st[wid][2][0];
            const float4* aBp = (const float4*)&s_st[wid][3][0];
            const float4* xAp = (const float4*)&s_st[wid][4][0];
            const float4* xBp = (const float4*)&s_st[wid][5][0];

#pragma unroll
            for (int c4 = 0; c4 < 4; c4++) {
                float4 x4A = xAp[c4], ax4A = xAp[4 + c4];
                float4 x4B = xBp[c4], ax4B = xBp[4 + c4];
#pragma unroll
                for (int u = 0; u < 4; u++) {
                    float4 w = s_wx4[(c4 * 4 + u) * CH + lane];
                    float xa = GETC(x4A, u), aa = GETC(ax4A, u);
                    float xb = GETC(x4B, u), ab = GETC(ax4B, u);
                    zA += xa * w.x + aa * w.y;  rA += xa * w.z + aa * w.w;
                    zB += xb * w.x + ab * w.y;  rB += xb * w.z + ab * w.w;
                }
            }
#pragma unroll
            for (int c4 = 0; c4 < 8; c4++) {
                float4 h4A = hAp[c4], a4A = aAp[c4];
                float4 h4B = hBp[c4], a4B = aBp[c4];
#pragma unroll
                for (int u = 0; u < 4; u++) {
                    float4 w = s_wh4[(c4 * 4 + u) * CH + lane];
                    float ha = GETC(h4A, u), aa = GETC(a4A, u);
                    float hb = GETC(h4B, u), ab = GETC(a4B, u);
                    zA += ha * w.x + aa * w.y;  rA += ha * w.z + aa * w.w;
                    zB += hb * w.x + ab * w.y;  rB += hb * w.z + ab * w.w;
                }
            }
            zA = 1.f / (1.f + __expf(-zA));
            rA = 1.f / (1.f + __expf(-rA));
            zB = 1.f / (1.f + __expf(-zB));
            rB = 1.f / (1.f + __expf(-rB));
            float hrA = hA * rA, hrB = hB * rB;
            g_Z  [nA * CH + lane] = zA;   g_hR  [nA * CH + lane] = hrA;
            g_Z  [nB_ * CH + lane] = zB;  g_hR  [nB_ * CH + lane] = hrB;
            g_hR16[nA * CH + lane] = __float2half(hrA);
            g_hR16[nB_ * CH + lane] = __float2half(hrB);
            __syncwarp();
        }

        // ---------------- grid barrier ----------------
        gen++;
        __syncthreads();
        if (tid == 0) {
            __threadfence();
            if (atomicAdd(&g_cnt, 1) == NB - 1) {
                g_cnt = 0;
                __threadfence();
                g_release = gen;
            } else {
                while (g_release < gen) { }
            }
        }
        __syncthreads();

        // ---------------- phase B: candidate + blend + fc out -------------
        for (int p = gw; p < NN / 2; p += nwarp) {
            int nA = 2 * p, nB_ = 2 * p + 1;
            float hA  = g_h [nA * CH + lane];
            float hB  = g_h [nB_ * CH + lane];
            float hrA = g_hR[nA * CH + lane];
            float hrB = g_hR[nB_ * CH + lane];
            float zA  = g_Z [nA * CH + lane];
            float zB  = g_Z [nB_ * CH + lane];
            float xpA, xpB;
            if (lane < 16) {
                xpA = Xt[nA * CIN + cx];
                xpB = Xt[nB_ * CIN + cx];
            } else {
                xpA = __half2float(AXt[nA * CIN + cx]);
                xpB = __half2float(AXt[nB_ * CIN + cx]);
            }
            float aA = gather_h16(g_hR16, nA, lane);
            float aB = gather_h16(g_hR16, nB_, lane);

            s_st[wid][0][lane] = hrA; s_st[wid][1][lane] = aA;
            s_st[wid][2][lane] = hrB; s_st[wid][3][lane] = aB;
            s_st[wid][4][lane] = xpA; s_st[wid][5][lane] = xpB;
            __syncwarp();

            float cA = s_bh[lane], cB = cA;
            const float4* hAp = (const float4*)&s_st[wid][0][0];
            const float4* aAp = (const float4*)&s_st[wid][1][0];
            const float4* hBp = (const float4*)&s_st[wid][2][0];
            const float4* aBp = (const float4*)&s_st[wid][3][0];
            const float4* xAp = (const float4*)&s_st[wid][4][0];
            const float4* xBp = (const float4*)&s_st[wid][5][0];

#pragma unroll
            for (int c4 = 0; c4 < 4; c4++) {
                float4 x4A = xAp[c4], ax4A = xAp[4 + c4];
                float4 x4B = xBp[c4], ax4B = xBp[4 + c4];
#pragma unroll
                for (int u = 0; u < 4; u++) {
                    float2 w = s_wx2[(c4 * 4 + u) * CH + lane];
                    cA += GETC(x4A, u) * w.x + GETC(ax4A, u) * w.y;
                    cB += GETC(x4B, u) * w.x + GETC(ax4B, u) * w.y;
                }
            }
#pragma unroll
            for (int c4 = 0; c4 < 8; c4++) {
                float4 h4A = hAp[c4], a4A = aAp[c4];
                float4 h4B = hBp[c4], a4B = aBp[c4];
#pragma unroll
                for (int u = 0; u < 4; u++) {
                    float2 w = s_wh2[(c4 * 4 + u) * CH + lane];
                    cA += GETC(h4A, u) * w.x + GETC(a4A, u) * w.y;
                    cB += GETC(h4B, u) * w.x + GETC(a4B, u) * w.y;
                }
            }
            float hnA = zA * hA + (1.f - zA) * tanhf(cA);
            float hnB = zB * hB + (1.f - zB) * tanhf(cB);
            g_h[nA * CH + lane] = hnA;
            g_h[nB_ * CH + lane] = hnB;
            g_h16[nA * CH + lane] = __float2half(hnA);
            g_h16[nB_ * CH + lane] = __float2half(hnB);

            s_st[wid][6][lane] = hnA;
            s_st[wid][7][lane] = hnB;
            __syncwarp();
            if (lane < 16) {
                int node = lane >> 3, j = lane & 7;
                const float* hn = &s_st[wid][6 + node][0];
                float acc = s_fcb[j];
#pragma unroll
                for (int c = 0; c < CH; c++) acc += hn[c] * s_fcw[c * COUTC + j];
                int n = node ? nB_ : nA;
                out[((size_t)t * NN + n) * COUTC + j] = acc;
            }
            __syncwarp();
        }

        // ---------------- grid barrier (h published for next step) --------
        gen++;
        __syncthreads();
        if (tid == 0) {
            __threadfence();
            if (atomicAdd(&g_cnt, 1) == NB - 1) {
                g_cnt = 0;
                __threadfence();
                g_release = gen;
            } else {
                while (g_release < gen) { }
            }
        }
        __syncthreads();
    }
}

// ---------------- launch ----------------
extern "C" void kernel_launch(void* const* d_in, const int* in_sizes, int n_in,
                              void* d_out, int out_size) {
    const float* X   = (const float*)d_in[0];
    const void*  ei  = d_in[1];
    const float* Wxz = (const float*)d_in[2];
    const float* bxz = (const float*)d_in[3];
    const float* Whz = (const float*)d_in[4];
    const float* bhz = (const float*)d_in[5];
    const float* Wxr = (const float*)d_in[6];
    const float* bxr = (const float*)d_in[7];
    const float* Whr = (const float*)d_in[8];
    const float* bhr = (const float*)d_in[9];
    const float* Wxh = (const float*)d_in[10];
    const float* bxh = (const float*)d_in[11];
    const float* Whh = (const float*)d_in[12];
    const float* bhh = (const float*)d_in[13];
    const float* fcw = (const float*)d_in[14];
    const float* fcb = (const float*)d_in[15];
    float* out = (float*)d_out;

    int E = in_sizes[1] / 2;

    // preprocess: count(0), scan(1), fill(2), ax(3)
    k_count<<<(E + 255) / 256, 256>>>(ei, X, E);
    k_scan<<<1, 1024>>>();
    k_fill<<<(E + 255) / 256, 256>>>(ei, E);
    k_ax<<<(TT / 2) * (NN / 8), 256>>>();

    // persistent recurrence: ONE launch for all 128 steps
    k_gru<<<NB, 256>>>(X, Wxz, bxz, Whz, bhz, Wxr, bxr, Whr, bhr,
                       Wxh, bxh, Whh, bhh, fcw, fcb, out);
}

// round 11
// speedup vs baseline: 1.3649x; 1.1142x over previous
#include <cuda_runtime.h>
#include <cuda_fp16.h>
#include <cstdint>

// Problem constants (fixed shapes for this problem)
#define TT    128
#define NN    50000
#define EE    1600000
#define CIN   16
#define CH    32
#define COUTC 8
#define NB    592          // persistent grid: 148 SMs x 4 blocks (co-resident)
#define TILES 3125         // NN / 16
#define APAD  104          // A/B-phase smem row pad (halfs) -> conflict-free frags
#define BPAD  100          // phase-B weight row pad
#define FULL  0xFFFFFFFFu

// ---------------- scratch (device globals; no runtime allocation) ----------
__device__ int   g_is64;
__device__ int   g_cnt_src[NN];
__device__ int   g_cnt_dst[NN];
__device__ int   g_cursor[NN];
__device__ int   g_off[NN + 1];
__device__ float g_dinv[NN];
__device__ __align__(16) int2   g_csr[EE];          // {src, w-bits}
__device__ __align__(16) float  g_h[NN * CH];
__device__ float  g_Z[NN * CH];
__device__ __align__(16) __half g_h16[NN * CH];     // fp16 gather mirror of h
__device__ __align__(16) __half g_hR16[NN * CH];    // fp16 gather mirror of h*R
__device__ __align__(16) __half g_X16[(size_t)TT * NN * CIN];   // fp16 X
__device__ __align__(16) __half g_AX16[(size_t)TT * NN * CIN];  // fp16 agg(x_t)

// software grid barrier state (reset each replay by k_count)
__device__ int          g_cnt;
__device__ volatile int g_release;

// fp16 load bypassing L1 (cross-SM producer/consumer inside one kernel)
__device__ __forceinline__ float ldcg_h(const __half* p) {
    unsigned short v = __ldcg((const unsigned short*)p);
    __half_raw r; r.x = v;
    return __half2float(*(__half*)&r);
}

// m16n8k16 fp16 MMA, fp32 accumulate
__device__ __forceinline__ void mma16816(float& c0, float& c1, float& c2, float& c3,
                                         unsigned a0, unsigned a1, unsigned a2, unsigned a3,
                                         unsigned b0, unsigned b1) {
    asm volatile(
        "mma.sync.aligned.m16n8k16.row.col.f32.f16.f16.f32 "
        "{%0,%1,%2,%3}, {%4,%5,%6,%7}, {%8,%9}, {%0,%1,%2,%3};"
        : "+f"(c0), "+f"(c1), "+f"(c2), "+f"(c3)
        : "r"(a0), "r"(a1), "r"(a2), "r"(a3), "r"(b0), "r"(b1));
}

// ---------------- launch 0: count + zero + X->fp16 + dtype detect ----------
__global__ void __launch_bounds__(256) k_count(const void* __restrict__ ei,
                                               const float* __restrict__ X, int E) {
    int tid0 = blockIdx.x * blockDim.x + threadIdx.x;
    int stride = gridDim.x * blockDim.x;

    long long v = ((const long long*)ei)[threadIdx.x];
    int bad = (v < 0 || v >= NN) ? 1 : 0;
    int anybad = __syncthreads_or(bad);
    int is64 = anybad ? 0 : 1;
    if (tid0 == 0) { g_is64 = is64; g_cnt = 0; g_release = 0; }

    if (tid0 < E) {
        long long sl, dl;
        if (is64) {
            sl = ((const long long*)ei)[tid0];
            dl = ((const long long*)ei)[(size_t)E + tid0];
        } else {
            sl = ((const int*)ei)[tid0];
            dl = ((const int*)ei)[E + tid0];
        }
        if (sl >= 0 && sl < NN) atomicAdd(&g_cnt_src[(int)sl], 1);
        if (dl >= 0 && dl < NN) atomicAdd(&g_cnt_dst[(int)dl], 1);
    }

    for (int i = tid0; i < NN * CH; i += stride) {
        g_h[i] = 0.f;
        g_h16[i] = __float2half(0.f);
    }

    const size_t XT4 = (size_t)TT * NN * CIN / 4;
    const float4* X4 = (const float4*)X;
    __half2* X16 = (__half2*)g_X16;
    for (size_t i = tid0; i < XT4; i += stride) {
        float4 x = X4[i];
        X16[i * 2]     = __floats2half2_rn(x.x, x.y);
        X16[i * 2 + 1] = __floats2half2_rn(x.z, x.w);
    }
}

// ---------------- launch 1: dinv + exclusive scan (single block) -----------
__global__ void __launch_bounds__(1024) k_scan() {
    __shared__ int s[1024];
    __shared__ int carry_s;
    int tid = threadIdx.x;
    for (int n = tid; n < NN; n += 1024) {
        int dsrc = g_cnt_src[n];
        g_dinv[n] = (dsrc > 0) ? rsqrtf((float)dsrc) : 0.f;
    }
    if (tid == 0) carry_s = 0;
    __syncthreads();
    for (int base = 0; base < NN; base += 1024) {
        int i = base + tid;
        int v = (i < NN) ? g_cnt_dst[i] : 0;
        s[tid] = v;
        __syncthreads();
        for (int off = 1; off < 1024; off <<= 1) {
            int x = (tid >= off) ? s[tid - off] : 0;
            __syncthreads();
            s[tid] += x;
            __syncthreads();
        }
        if (i < NN) g_off[i] = carry_s + s[tid] - v;
        __syncthreads();
        if (tid == 0) carry_s += s[1023];
        __syncthreads();
    }
    if (tid == 0) g_off[NN] = carry_s;
}

// ---------------- launch 2: fill CSR ----------------
__global__ void k_fill(const void* __restrict__ ei, int E) {
    int i = blockIdx.x * blockDim.x + threadIdx.x;
    if (i >= E) return;
    long long sl, dl;
    if (g_is64) {
        sl = ((const long long*)ei)[i];
        dl = ((const long long*)ei)[(size_t)E + i];
    } else {
        sl = ((const int*)ei)[i];
        dl = ((const int*)ei)[E + i];
    }
    if (sl < 0 || sl >= NN || dl < 0 || dl >= NN) return;
    int s = (int)sl, d = (int)dl;
    int pos = g_off[d] + atomicAdd(&g_cursor[d], 1);
    g_csr[pos] = make_int2(s, __float_as_int(-g_dinv[s] * g_dinv[d]));
}

// ---------------- launch 3: AX precompute + counter re-zero ----------------
__global__ void __launch_bounds__(256, 4) k_ax() {
    int gi = blockIdx.x * 256 + threadIdx.x;
    if (gi < NN) { g_cnt_src[gi] = 0; g_cnt_dst[gi] = 0; g_cursor[gi] = 0; }

    int warp = threadIdx.x >> 5, lane = threadIdx.x & 31;
    int tp = blockIdx.x / (NN / 8);
    int nb = blockIdx.x % (NN / 8);
    int n  = nb * 8 + warp;
    int t  = tp * 2 + (lane >> 4);
    int ch = lane & 15;
    const __half* Xt = g_X16 + (size_t)t * NN * CIN;

    int i = g_off[n], end = g_off[n + 1];
    float a0 = 0.f, a1 = 0.f, a2 = 0.f, a3 = 0.f;
    for (; i + 4 <= end; i += 4) {
        int2 e0 = g_csr[i], e1 = g_csr[i + 1], e2 = g_csr[i + 2], e3 = g_csr[i + 3];
        a0 += __int_as_float(e0.y) * __half2float(Xt[e0.x * CIN + ch]);
        a1 += __int_as_float(e1.y) * __half2float(Xt[e1.x * CIN + ch]);
        a2 += __int_as_float(e2.y) * __half2float(Xt[e2.x * CIN + ch]);
        a3 += __int_as_float(e3.y) * __half2float(Xt[e3.x * CIN + ch]);
    }
    for (; i < end; i++) {
        int2 e = g_csr[i];
        a0 += __int_as_float(e.y) * __half2float(Xt[e.x * CIN + ch]);
    }
    g_AX16[((size_t)t * NN + n) * CIN + ch] = __float2half((a0 + a1) + (a2 + a3));
}

// ---------------- gather: warp-uniform CSR, fp16 source via L2, MLP=4 -----
__device__ __forceinline__ float gather_h16(const __half* __restrict__ src, int n, int lane) {
    int i = g_off[n], end = g_off[n + 1];
    float a0 = 0.f, a1 = 0.f, a2 = 0.f, a3 = 0.f;
    for (; i + 4 <= end; i += 4) {
        int2 e0 = g_csr[i], e1 = g_csr[i + 1], e2 = g_csr[i + 2], e3 = g_csr[i + 3];
        a0 += __int_as_float(e0.y) * ldcg_h(&src[e0.x * CH + lane]);
        a1 += __int_as_float(e1.y) * ldcg_h(&src[e1.x * CH + lane]);
        a2 += __int_as_float(e2.y) * ldcg_h(&src[e2.x * CH + lane]);
        a3 += __int_as_float(e3.y) * ldcg_h(&src[e3.x * CH + lane]);
    }
    for (; i < end; i++) {
        int2 e = g_csr[i];
        a0 += __int_as_float(e.y) * ldcg_h(&src[e.x * CH + lane]);
    }
    return (a0 + a1) + (a2 + a3);
}

// ---------------- persistent recurrence kernel (tensor-core dense) --------
// 592 blocks x 256 thr (8 warps), co-resident. Block processes 16-node tiles.
// Dense per tile: A[16x96]=[x|ax|h|agg] fp16 @ B[96x64] split-fp16 weights.
__global__ void __launch_bounds__(256, 4) k_gru(
    const float* __restrict__ Wxz, const float* __restrict__ bxz,
    const float* __restrict__ Whz, const float* __restrict__ bhz,
    const float* __restrict__ Wxr, const float* __restrict__ bxr,
    const float* __restrict__ Whr, const float* __restrict__ bhr,
    const float* __restrict__ Wxh, const float* __restrict__ bxh,
    const float* __restrict__ Whh, const float* __restrict__ bhh,
    const float* __restrict__ fcw, const float* __restrict__ fcb,
    float* __restrict__ out)
{
    __shared__ __align__(16) __half sA[16][APAD];        // operand tile
    __shared__ __align__(16) __half sBAh[64][APAD];      // phase-A weights hi
    __shared__ __align__(16) __half sBAl[64][APAD];      // phase-A weights lo
    __shared__ __align__(16) __half sBBh[32][BPAD];      // phase-B weights hi
    __shared__ __align__(16) __half sBBl[32][BPAD];      // phase-B weights lo
    __shared__ __align__(16) float  sZT[16][68];         // fp32 acc/exchange tile
    __shared__ float s_bz[CH], s_br[CH], s_bh[CH];
    __shared__ float s_fcw[CH * COUTC], s_fcb[COUTC];

    int tid = threadIdx.x;
    int lane = tid & 31, wid = tid >> 5;

    // ---- stage weights: B row k maps A cols: [x(0..15)|ax(16..31)|h(32..63)|a(64..95)]
    for (int idx = tid; idx < 64 * 96; idx += 256) {
        int j = idx / 96, k = idx % 96;
        int jj = (j < 32) ? j : j - 32;
        const float* Wx = (j < 32) ? Wxz : Wxr;
        const float* Wh = (j < 32) ? Whz : Whr;
        float w;
        if      (k < 16) w = Wx[k * CH + jj];
        else if (k < 32) w = Wx[CIN * CH + (k - 16) * CH + jj];
        else if (k < 64) w = Wh[(k - 32) * CH + jj];
        else             w = Wh[CH * CH + (k - 64) * CH + jj];
        __half hi = __float2half_rn(w);
        sBAh[j][k] = hi;
        sBAl[j][k] = __float2half_rn(w - __half2float(hi));
    }
    for (int idx = tid; idx < 32 * 96; idx += 256) {
        int j = idx / 96, k = idx % 96;
        float w;
        if      (k < 16) w = Wxh[k * CH + j];
        else if (k < 32) w = Wxh[CIN * CH + (k - 16) * CH + j];
        else if (k < 64) w = Whh[(k - 32) * CH + j];
        else             w = Whh[CH * CH + (k - 64) * CH + j];
        __half hi = __float2half_rn(w);
        sBBh[j][k] = hi;
        sBBl[j][k] = __float2half_rn(w - __half2float(hi));
    }
    for (int i = tid; i < CH * COUTC; i += 256) s_fcw[i] = fcw[i];
    if (tid < CH) {
        s_bz[tid] = bxz[tid] + bhz[tid];
        s_br[tid] = bxr[tid] + bhr[tid];
        s_bh[tid] = bxh[tid] + bhh[tid];
    }
    if (tid < COUTC) s_fcb[tid] = fcb[tid];
    __syncthreads();

    int g = lane >> 2, tq = lane & 3;       // mma group / thread-in-group
    int r0 = 2 * wid, r1 = r0 + 1;          // tile rows owned by this warp

    int gen = 0;
    for (int t = 0; t < TT; t++) {
        const __half* Xt  = g_X16  + (size_t)t * NN * CIN;
        const __half* AXt = g_AX16 + (size_t)t * NN * CIN;

        // ================= phase A: z, r, h*R =================
        for (int tile = blockIdx.x; tile < TILES; tile += NB) {
            int n0 = tile * 16;
            int nA = n0 + r0, nB = n0 + r1;
            // stage x|ax (cols 0..31)
            __half xv0, xv1;
            if (lane < 16) { xv0 = Xt[nA * CIN + lane];        xv1 = Xt[nB * CIN + lane]; }
            else           { xv0 = AXt[nA * CIN + lane - 16];  xv1 = AXt[nB * CIN + lane - 16]; }
            sA[r0][lane] = xv0;
            sA[r1][lane] = xv1;
            // stage h (cols 32..63) — own nodes, written by this block last step
            sA[r0][32 + lane] = g_h16[nA * CH + lane];
            sA[r1][32 + lane] = g_h16[nB * CH + lane];
            // gather agg(h) (cols 64..95)
            float aA = gather_h16(g_h16, nA, lane);
            float aB = gather_h16(g_h16, nB, lane);
            sA[r0][64 + lane] = __float2half(aA);
            sA[r1][64 + lane] = __float2half(aB);
            __syncthreads();

            // mma: warp owns output cols 8*wid .. 8*wid+7 of [z(0..31)|r(32..63)]
            float c0 = 0.f, c1 = 0.f, c2 = 0.f, c3 = 0.f;
            int j = 8 * wid + g;
#pragma unroll
            for (int kt = 0; kt < 6; kt++) {
                int kc = kt * 16 + 2 * tq;
                unsigned a0 = *(const unsigned*)&sA[g][kc];
                unsigned a1 = *(const unsigned*)&sA[g + 8][kc];
                unsigned a2 = *(const unsigned*)&sA[g][kc + 8];
                unsigned a3 = *(const unsigned*)&sA[g + 8][kc + 8];
                unsigned b0 = *(const unsigned*)&sBAh[j][kc];
                unsigned b1 = *(const unsigned*)&sBAh[j][kc + 8];
                mma16816(c0, c1, c2, c3, a0, a1, a2, a3, b0, b1);
                if (kt >= 2) {   // lo-split only for recurrent (h/a) weights
                    unsigned l0 = *(const unsigned*)&sBAl[j][kc];
                    unsigned l1 = *(const unsigned*)&sBAl[j][kc + 8];
                    mma16816(c0, c1, c2, c3, a0, a1, a2, a3, l0, l1);
                }
            }
            int jc = 8 * wid + 2 * tq;
            *(float2*)&sZT[g][jc]     = make_float2(c0, c1);
            *(float2*)&sZT[g + 8][jc] = make_float2(c2, c3);
            __syncthreads();

            // epilogue: 512 (node,channel) items
#pragma unroll
            for (int it = tid; it < 512; it += 256) {
                int n = it >> 5, c = it & 31;
                int gn = n0 + n;
                float z = 1.f / (1.f + __expf(-(sZT[n][c] + s_bz[c])));
                float r = 1.f / (1.f + __expf(-(sZT[n][32 + c] + s_br[c])));
                float hr = g_h[gn * CH + c] * r;
                g_Z[gn * CH + c] = z;
                g_hR16[gn * CH + c] = __float2half(hr);
            }
            __syncthreads();
        }

        // ---- grid barrier (hR16 published) ----
        gen++;
        __syncthreads();
        if (tid == 0) {
            __threadfence();
            if (atomicAdd(&g_cnt, 1) == NB - 1) {
                g_cnt = 0;
                __threadfence();
                g_release = gen;
            } else {
                while (g_release < gen) { }
            }
        }
        __syncthreads();

        // ================= phase B: candidate + blend + fc =================
        for (int tile = blockIdx.x; tile < TILES; tile += NB) {
            int n0 = tile * 16;
            int nA = n0 + r0, nB = n0 + r1;
            __half xv0, xv1;
            if (lane < 16) { xv0 = Xt[nA * CIN + lane];        xv1 = Xt[nB * CIN + lane]; }
            else           { xv0 = AXt[nA * CIN + lane - 16];  xv1 = AXt[nB * CIN + lane - 16]; }
            sA[r0][lane] = xv0;
            sA[r1][lane] = xv1;
            sA[r0][32 + lane] = g_hR16[nA * CH + lane];   // own nodes (this block wrote)
            sA[r1][32 + lane] = g_hR16[nB * CH + lane];
            float aA = gather_h16(g_hR16, nA, lane);
            float aB = gather_h16(g_hR16, nB, lane);
            sA[r0][64 + lane] = __float2half(aA);
            sA[r1][64 + lane] = __float2half(aB);
            __syncthreads();

            // warps 0..3: hi-weights (all kt); warps 4..7: lo-weights (kt>=2)
            float c0 = 0.f, c1 = 0.f, c2 = 0.f, c3 = 0.f;
            int wsub = wid & 3;
            int j = 8 * wsub + g;
            if (wid < 4) {
#pragma unroll
                for (int kt = 0; kt < 6; kt++) {
                    int kc = kt * 16 + 2 * tq;
                    unsigned a0 = *(const unsigned*)&sA[g][kc];
                    unsigned a1 = *(const unsigned*)&sA[g + 8][kc];
                    unsigned a2 = *(const unsigned*)&sA[g][kc + 8];
                    unsigned a3 = *(const unsigned*)&sA[g + 8][kc + 8];
                    unsigned b0 = *(const unsigned*)&sBBh[j][kc];
                    unsigned b1 = *(const unsigned*)&sBBh[j][kc + 8];
                    mma16816(c0, c1, c2, c3, a0, a1, a2, a3, b0, b1);
                }
            } else {
#pragma unroll
                for (int kt = 2; kt < 6; kt++) {
                    int kc = kt * 16 + 2 * tq;
                    unsigned a0 = *(const unsigned*)&sA[g][kc];
                    unsigned a1 = *(const unsigned*)&sA[g + 8][kc];
                    unsigned a2 = *(const unsigned*)&sA[g][kc + 8];
                    unsigned a3 = *(const unsigned*)&sA[g + 8][kc + 8];
                    unsigned b0 = *(const unsigned*)&sBBl[j][kc];
                    unsigned b1 = *(const unsigned*)&sBBl[j][kc + 8];
                    mma16816(c0, c1, c2, c3, a0, a1, a2, a3, b0, b1);
                }
            }
            int jc = ((wid < 4) ? 0 : 32) + 8 * wsub + 2 * tq;
            *(float2*)&sZT[g][jc]     = make_float2(c0, c1);
            *(float2*)&sZT[g + 8][jc] = make_float2(c2, c3);
            __syncthreads();

            // epilogue: hn = Z*h + (1-Z)*tanh(hi+lo+bias); stage hn for fc
            float hn[2];
#pragma unroll
            for (int q = 0; q < 2; q++) {
                int it = tid + q * 256;
                int n = it >> 5, c = it & 31;
                int gn = n0 + n;
                float ct = sZT[n][c] + sZT[n][32 + c] + s_bh[c];
                float z = g_Z[gn * CH + c];
                float h = g_h[gn * CH + c];
                float v = z * h + (1.f - z) * tanhf(ct);
                hn[q] = v;
                g_h[gn * CH + c] = v;
                g_h16[gn * CH + c] = __float2half(v);
            }
            __syncthreads();
#pragma unroll
            for (int q = 0; q < 2; q++) {
                int it = tid + q * 256;
                sZT[it >> 5][it & 31] = hn[q];
            }
            __syncthreads();
            if (tid < 128) {
                int n = tid >> 3, jj = tid & 7;
                float acc = s_fcb[jj];
#pragma unroll
                for (int c = 0; c < CH; c++) acc += sZT[n][c] * s_fcw[c * COUTC + jj];
                out[((size_t)t * NN + n0 + n) * COUTC + jj] = acc;
            }
            __syncthreads();
        }

        // ---- grid barrier (h published for next step) ----
        gen++;
        __syncthreads();
        if (tid == 0) {
            __threadfence();
            if (atomicAdd(&g_cnt, 1) == NB - 1) {
                g_cnt = 0;
                __threadfence();
                g_release = gen;
            } else {
                while (g_release < gen) { }
            }
        }
        __syncthreads();
    }
}

// ---------------- launch ----------------
extern "C" void kernel_launch(void* const* d_in, const int* in_sizes, int n_in,
                              void* d_out, int out_size) {
    const float* X   = (const float*)d_in[0];
    const void*  ei  = d_in[1];
    const float* Wxz = (const float*)d_in[2];
    const float* bxz = (const float*)d_in[3];
    const float* Whz = (const float*)d_in[4];
    const float* bhz = (const float*)d_in[5];
    const float* Wxr = (const float*)d_in[6];
    const float* bxr = (const float*)d_in[7];
    const float* Whr = (const float*)d_in[8];
    const float* bhr = (const float*)d_in[9];
    const float* Wxh = (const float*)d_in[10];
    const float* bxh = (const float*)d_in[11];
    const float* Whh = (const float*)d_in[12];
    const float* bhh = (const float*)d_in[13];
    const float* fcw = (const float*)d_in[14];
    const float* fcb = (const float*)d_in[15];
    float* out = (float*)d_out;

    int E = in_sizes[1] / 2;

    // preprocess: count(0), scan(1), fill(2), ax(3)
    k_count<<<(E + 255) / 256, 256>>>(ei, X, E);
    k_scan<<<1, 1024>>>();
    k_fill<<<(E + 255) / 256, 256>>>(ei, E);
    k_ax<<<(TT / 2) * (NN / 8), 256>>>();

    // persistent recurrence: ONE launch, tensor-core dense
    k_gru<<<NB, 256>>>(Wxz, bxz, Whz, bhz, Wxr, bxr, Whr, bhr,
                       Wxh, bxh, Whh, bhh, fcw, fcb, out);
}

// round 12
// speedup vs baseline: 2.0082x; 1.4713x over previous
#include <cuda_runtime.h>
#include <cuda_fp16.h>
#include <cstdint>

// Problem constants (fixed shapes for this problem)
#define TT     128
#define NN     50000
#define EE     1600000
#define EE_PAD 1800000     // padded CSR: each node list 4-aligned, len % 4 == 0
#define CIN    16
#define CH     32
#define COUTC  8
#define NB     592         // persistent grid: 148 SMs x 4 blocks (co-resident)
#define TILES  3125        // NN / 16
#define APAD   104         // smem row pad (halfs)
#define BPAD   100
#define FULL   0xFFFFFFFFu

// ---------------- scratch (device globals; no runtime allocation) ----------
__device__ int   g_is64;
__device__ int   g_cnt_src[NN];
__device__ int   g_cnt_dst[NN];
__device__ int   g_cursor[NN];
__device__ int   g_off[NN + 1];
__device__ float g_dinv[NN];
__device__ __align__(16) int2   g_csr[EE_PAD];      // {src, w-bits}; pads = {0,0}
__device__ __align__(16) float  g_h[NN * CH];
__device__ float  g_Z[NN * CH];
__device__ __align__(16) __half g_h16[NN * CH];     // fp16 gather mirror of h
__device__ __align__(16) __half g_hR16[NN * CH];    // fp16 gather mirror of h*R
__device__ __align__(16) __half g_X16[(size_t)TT * NN * CIN];   // fp16 X
__device__ __align__(16) __half g_AX16[(size_t)TT * NN * CIN];  // fp16 agg(x_t)

// software grid barrier state (reset each replay by k_count)
__device__ int          g_cnt;
__device__ volatile int g_release;

// half2 load bypassing L1 (cross-SM producer/consumer inside one kernel)
__device__ __forceinline__ __half2 ldcg_h2(const __half* p) {
    unsigned v = __ldcg((const unsigned*)p);
    return *(__half2*)&v;
}

// m16n8k16 fp16 MMA, fp32 accumulate
__device__ __forceinline__ void mma16816(float& c0, float& c1, float& c2, float& c3,
                                         unsigned a0, unsigned a1, unsigned a2, unsigned a3,
                                         unsigned b0, unsigned b1) {
    asm volatile(
        "mma.sync.aligned.m16n8k16.row.col.f32.f16.f16.f32 "
        "{%0,%1,%2,%3}, {%4,%5,%6,%7}, {%8,%9}, {%0,%1,%2,%3};"
        : "+f"(c0), "+f"(c1), "+f"(c2), "+f"(c3)
        : "r"(a0), "r"(a1), "r"(a2), "r"(a3), "r"(b0), "r"(b1));
}

// pair gather: lane's half-warp owns node n, lane covers channels (2cl, 2cl+1).
// CSR padded: beg 4-aligned, length multiple of 4, pad edges {0, w=0}.
__device__ __forceinline__ void gather_pair(const __half* __restrict__ src,
                                            int n, int cl, float& o0, float& o1) {
    int beg = g_off[n], end = g_off[n + 1];
    int c2 = 2 * cl;
    float x0 = 0.f, y0 = 0.f, x1 = 0.f, y1 = 0.f;
    for (int i = beg; i < end; i += 4) {
        int4 qa = *(const int4*)&g_csr[i];
        int4 qb = *(const int4*)&g_csr[i + 2];
        __half2 v0 = ldcg_h2(&src[qa.x * CH + c2]);
        __half2 v1 = ldcg_h2(&src[qa.z * CH + c2]);
        __half2 v2 = ldcg_h2(&src[qb.x * CH + c2]);
        __half2 v3 = ldcg_h2(&src[qb.z * CH + c2]);
        float w0 = __int_as_float(qa.y), w1 = __int_as_float(qa.w);
        float w2 = __int_as_float(qb.y), w3 = __int_as_float(qb.w);
        float2 f0 = __half22float2(v0), f1 = __half22float2(v1);
        float2 f2 = __half22float2(v2), f3 = __half22float2(v3);
        x0 += w0 * f0.x;  y0 += w0 * f0.y;
        x1 += w1 * f1.x;  y1 += w1 * f1.y;
        x0 += w2 * f2.x;  y0 += w2 * f2.y;
        x1 += w3 * f3.x;  y1 += w3 * f3.y;
    }
    o0 = x0 + x1;
    o1 = y0 + y1;
}

// ---------------- launch 0: count + zero + X->fp16 + dtype detect ----------
__global__ void __launch_bounds__(256) k_count(const void* __restrict__ ei,
                                               const float* __restrict__ X, int E) {
    int tid0 = blockIdx.x * blockDim.x + threadIdx.x;
    int stride = gridDim.x * blockDim.x;

    long long v = ((const long long*)ei)[threadIdx.x];
    int bad = (v < 0 || v >= NN) ? 1 : 0;
    int anybad = __syncthreads_or(bad);
    int is64 = anybad ? 0 : 1;
    if (tid0 == 0) { g_is64 = is64; g_cnt = 0; g_release = 0; }

    if (tid0 < E) {
        long long sl, dl;
        if (is64) {
            sl = ((const long long*)ei)[tid0];
            dl = ((const long long*)ei)[(size_t)E + tid0];
        } else {
            sl = ((const int*)ei)[tid0];
            dl = ((const int*)ei)[E + tid0];
        }
        if (sl >= 0 && sl < NN) atomicAdd(&g_cnt_src[(int)sl], 1);
        if (dl >= 0 && dl < NN) atomicAdd(&g_cnt_dst[(int)dl], 1);
    }

    for (int i = tid0; i < NN * CH; i += stride) {
        g_h[i] = 0.f;
        g_h16[i] = __float2half(0.f);
    }
    // pre-zero padded CSR (pad entries stay {src=0, w=0})
    for (int i = tid0; i < EE_PAD; i += stride) g_csr[i] = make_int2(0, 0);

    const size_t XT4 = (size_t)TT * NN * CIN / 4;
    const float4* X4 = (const float4*)X;
    __half2* X16 = (__half2*)g_X16;
    for (size_t i = tid0; i < XT4; i += stride) {
        float4 x = X4[i];
        X16[i * 2]     = __floats2half2_rn(x.x, x.y);
        X16[i * 2 + 1] = __floats2half2_rn(x.z, x.w);
    }
}

// ---------------- launch 1: dinv + PADDED exclusive scan (single block) ----
__global__ void __launch_bounds__(1024) k_scan() {
    __shared__ int s[1024];
    __shared__ int carry_s;
    int tid = threadIdx.x;
    for (int n = tid; n < NN; n += 1024) {
        int dsrc = g_cnt_src[n];
        g_dinv[n] = (dsrc > 0) ? rsqrtf((float)dsrc) : 0.f;
    }
    if (tid == 0) carry_s = 0;
    __syncthreads();
    for (int base = 0; base < NN; base += 1024) {
        int i = base + tid;
        int v = (i < NN) ? ((g_cnt_dst[i] + 3) & ~3) : 0;   // pad to multiple of 4
        s[tid] = v;
        __syncthreads();
        for (int off = 1; off < 1024; off <<= 1) {
            int x = (tid >= off) ? s[tid - off] : 0;
            __syncthreads();
            s[tid] += x;
            __syncthreads();
        }
        if (i < NN) g_off[i] = carry_s + s[tid] - v;
        __syncthreads();
        if (tid == 0) carry_s += s[1023];
        __syncthreads();
    }
    if (tid == 0) g_off[NN] = carry_s;
}

// ---------------- launch 2: fill CSR ----------------
__global__ void k_fill(const void* __restrict__ ei, int E) {
    int i = blockIdx.x * blockDim.x + threadIdx.x;
    if (i >= E) return;
    long long sl, dl;
    if (g_is64) {
        sl = ((const long long*)ei)[i];
        dl = ((const long long*)ei)[(size_t)E + i];
    } else {
        sl = ((const int*)ei)[i];
        dl = ((const int*)ei)[E + i];
    }
    if (sl < 0 || sl >= NN || dl < 0 || dl >= NN) return;
    int s = (int)sl, d = (int)dl;
    int pos = g_off[d] + atomicAdd(&g_cursor[d], 1);
    g_csr[pos] = make_int2(s, __float_as_int(-g_dinv[s] * g_dinv[d]));
}

// ---------------- launch 3: persistent kernel (AX prologue + recurrence) ---
// 592 blocks x 256 thr (8 warps), co-resident. Block processes 16-node tiles.
// Dense per tile: A[16x96]=[x|ax|h|agg] fp16 @ B[96x64] split-fp16 weights.
__global__ void __launch_bounds__(256, 4) k_gru(
    const float* __restrict__ Wxz, const float* __restrict__ bxz,
    const float* __restrict__ Whz, const float* __restrict__ bhz,
    const float* __restrict__ Wxr, const float* __restrict__ bxr,
    const float* __restrict__ Whr, const float* __restrict__ bhr,
    const float* __restrict__ Wxh, const float* __restrict__ bxh,
    const float* __restrict__ Whh, const float* __restrict__ bhh,
    const float* __restrict__ fcw, const float* __restrict__ fcb,
    float* __restrict__ out)
{
    __shared__ __align__(16) __half sA[16][APAD];        // operand tile
    __shared__ __align__(16) __half sBAh[64][APAD];      // phase-A weights hi
    __shared__ __align__(16) __half sBAl[64][APAD];      // phase-A weights lo
    __shared__ __align__(16) __half sBBh[32][BPAD];      // phase-B weights hi
    __shared__ __align__(16) __half sBBl[32][BPAD];      // phase-B weights lo
    __shared__ __align__(16) float  sZT[16][68];         // fp32 acc/exchange tile
    __shared__ float s_bz[CH], s_br[CH], s_bh[CH];
    __shared__ float s_fcw[CH * COUTC], s_fcb[COUTC];

    int tid = threadIdx.x;
    int lane = tid & 31, wid = tid >> 5;

    // ---- stage weights: B row k maps A cols: [x(0..15)|ax(16..31)|h(32..63)|a(64..95)]
    for (int idx = tid; idx < 64 * 96; idx += 256) {
        int j = idx / 96, k = idx % 96;
        int jj = (j < 32) ? j : j - 32;
        const float* Wx = (j < 32) ? Wxz : Wxr;
        const float* Wh = (j < 32) ? Whz : Whr;
        float w;
        if      (k < 16) w = Wx[k * CH + jj];
        else if (k < 32) w = Wx[CIN * CH + (k - 16) * CH + jj];
        else if (k < 64) w = Wh[(k - 32) * CH + jj];
        else             w = Wh[CH * CH + (k - 64) * CH + jj];
        __half hi = __float2half_rn(w);
        sBAh[j][k] = hi;
        sBAl[j][k] = __float2half_rn(w - __half2float(hi));
    }
    for (int idx = tid; idx < 32 * 96; idx += 256) {
        int j = idx / 96, k = idx % 96;
        float w;
        if      (k < 16) w = Wxh[k * CH + j];
        else if (k < 32) w = Wxh[CIN * CH + (k - 16) * CH + j];
        else if (k < 64) w = Whh[(k - 32) * CH + j];
        else             w = Whh[CH * CH + (k - 64) * CH + j];
        __half hi = __float2half_rn(w);
        sBBh[j][k] = hi;
        sBBl[j][k] = __float2half_rn(w - __half2float(hi));
    }
    for (int i = tid; i < CH * COUTC; i += 256) s_fcw[i] = fcw[i];
    if (tid < CH) {
        s_bz[tid] = bxz[tid] + bhz[tid];
        s_br[tid] = bxr[tid] + bhr[tid];
        s_bh[tid] = bxh[tid] + bhh[tid];
    }
    if (tid < COUTC) s_fcb[tid] = fcb[tid];
    __syncthreads();

    // ---- prologue: counter rezero + AX precompute (warp = node x 4 timesteps)
    for (int i = blockIdx.x * 256 + tid; i < NN; i += NB * 256) {
        g_cnt_src[i] = 0; g_cnt_dst[i] = 0; g_cursor[i] = 0;
    }
    {
        int tsub = lane >> 3;          // 0..3 timestep-in-quad
        int cl8  = lane & 7;           // channel pair (2cl8, 2cl8+1) of 16
        int gwarp = blockIdx.x * 8 + wid;
        for (int u = gwarp; u < NN * (TT / 4); u += NB * 8) {
            int tq = u / NN, n = u - tq * NN;
            int t = tq * 4 + tsub;
            const __half* Xt = g_X16 + (size_t)t * NN * CIN;
            int beg = g_off[n], end = g_off[n + 1];
            int c2 = 2 * cl8;
            float x0 = 0.f, y0 = 0.f, x1 = 0.f, y1 = 0.f;
            for (int i = beg; i < end; i += 4) {
                int4 qa = *(const int4*)&g_csr[i];
                int4 qb = *(const int4*)&g_csr[i + 2];
                float2 f0 = __half22float2(*(const __half2*)&Xt[qa.x * CIN + c2]);
                float2 f1 = __half22float2(*(const __half2*)&Xt[qa.z * CIN + c2]);
                float2 f2 = __half22float2(*(const __half2*)&Xt[qb.x * CIN + c2]);
                float2 f3 = __half22float2(*(const __half2*)&Xt[qb.z * CIN + c2]);
                float w0 = __int_as_float(qa.y), w1 = __int_as_float(qa.w);
                float w2 = __int_as_float(qb.y), w3 = __int_as_float(qb.w);
                x0 += w0 * f0.x;  y0 += w0 * f0.y;
                x1 += w1 * f1.x;  y1 += w1 * f1.y;
                x0 += w2 * f2.x;  y0 += w2 * f2.y;
                x1 += w3 * f3.x;  y1 += w3 * f3.y;
            }
            *(__half2*)&g_AX16[((size_t)t * NN + n) * CIN + c2] =
                __floats2half2_rn(x0 + x1, y0 + y1);
        }
    }

    int gen = 1;   // AX barrier
    __syncthreads();
    if (tid == 0) {
        __threadfence();
        if (atomicAdd(&g_cnt, 1) == NB - 1) {
            g_cnt = 0;
            __threadfence();
            g_release = gen;
        } else {
            while (g_release < gen) { }
        }
    }
    __syncthreads();

    int g = lane >> 2, tq4 = lane & 3;      // mma group / thread-in-group
    int r0 = 2 * wid, r1 = r0 + 1;          // tile rows owned by this warp
    int hw = lane >> 4, cl = lane & 15;     // pair-gather half / channel-pair
    int c2 = 2 * cl;

    for (int t = 0; t < TT; t++) {
        const __half* Xt  = g_X16  + (size_t)t * NN * CIN;
        const __half* AXt = g_AX16 + (size_t)t * NN * CIN;

        // ================= phase A: z, r, h*R =================
        for (int tile = blockIdx.x; tile < TILES; tile += NB) {
            int n0 = tile * 16;
            int nA = n0 + r0, nB = n0 + r1;
            int n = hw ? nB : nA;
            int r = hw ? r1 : r0;
            // x|ax (cols 0..31)
            __half2 xv = (cl < 8) ? *(const __half2*)&Xt[n * CIN + c2]
                                  : *(const __half2*)&AXt[n * CIN + (c2 - 16)];
            *(__half2*)&sA[r][c2] = xv;
            // h (cols 32..63) — own nodes, written by this block last step
            *(__half2*)&sA[r][32 + c2] = *(const __half2*)&g_h16[n * CH + c2];
            // gather agg(h) (cols 64..95)
            float e0, e1;
            gather_pair(g_h16, n, cl, e0, e1);
            *(__half2*)&sA[r][64 + c2] = __floats2half2_rn(e0, e1);
            __syncthreads();

            // mma: warp owns output cols 8*wid..8*wid+7 of [z(0..31)|r(32..63)]
            float c0 = 0.f, c1 = 0.f, cc2 = 0.f, c3 = 0.f;
            int j = 8 * wid + g;
#pragma unroll
            for (int kt = 0; kt < 6; kt++) {
                int kc = kt * 16 + 2 * tq4;
                unsigned a0 = *(const unsigned*)&sA[g][kc];
                unsigned a1 = *(const unsigned*)&sA[g + 8][kc];
                unsigned a2 = *(const unsigned*)&sA[g][kc + 8];
                unsigned a3 = *(const unsigned*)&sA[g + 8][kc + 8];
                unsigned b0 = *(const unsigned*)&sBAh[j][kc];
                unsigned b1 = *(const unsigned*)&sBAh[j][kc + 8];
                mma16816(c0, c1, cc2, c3, a0, a1, a2, a3, b0, b1);
                if (kt >= 2) {   // lo-split only for recurrent (h/a) weights
                    unsigned l0 = *(const unsigned*)&sBAl[j][kc];
                    unsigned l1 = *(const unsigned*)&sBAl[j][kc + 8];
                    mma16816(c0, c1, cc2, c3, a0, a1, a2, a3, l0, l1);
                }
            }
            int jc = 8 * wid + 2 * tq4;
            *(float2*)&sZT[g][jc]     = make_float2(c0, c1);
            *(float2*)&sZT[g + 8][jc] = make_float2(cc2, c3);
            __syncthreads();

            // epilogue: 512 (node,channel) items
#pragma unroll
            for (int it = tid; it < 512; it += 256) {
                int nn = it >> 5, c = it & 31;
                int gn = n0 + nn;
                float z = 1.f / (1.f + __expf(-(sZT[nn][c] + s_bz[c])));
                float rr = 1.f / (1.f + __expf(-(sZT[nn][32 + c] + s_br[c])));
                float hr = g_h[gn * CH + c] * rr;
                g_Z[gn * CH + c] = z;
                g_hR16[gn * CH + c] = __float2half(hr);
            }
            __syncthreads();
        }

        // ---- grid barrier (hR16 published) ----
        gen++;
        __syncthreads();
        if (tid == 0) {
            __threadfence();
            if (atomicAdd(&g_cnt, 1) == NB - 1) {
                g_cnt = 0;
                __threadfence();
                g_release = gen;
            } else {
                while (g_release < gen) { }
            }
        }
        __syncthreads();

        // ================= phase B: candidate + blend + fc =================
        for (int tile = blockIdx.x; tile < TILES; tile += NB) {
            int n0 = tile * 16;
            int nA = n0 + r0, nB = n0 + r1;
            int n = hw ? nB : nA;
            int r = hw ? r1 : r0;
            __half2 xv = (cl < 8) ? *(const __half2*)&Xt[n * CIN + c2]
                                  : *(const __half2*)&AXt[n * CIN + (c2 - 16)];
            *(__half2*)&sA[r][c2] = xv;
            *(__half2*)&sA[r][32 + c2] = *(const __half2*)&g_hR16[n * CH + c2];
            float e0, e1;
            gather_pair(g_hR16, n, cl, e0, e1);
            *(__half2*)&sA[r][64 + c2] = __floats2half2_rn(e0, e1);
            __syncthreads();

            // warps 0..3: hi-weights (all kt); warps 4..7: lo-weights (kt>=2)
            float c0 = 0.f, c1 = 0.f, cc2 = 0.f, c3 = 0.f;
            int wsub = wid & 3;
            int j = 8 * wsub + g;
            if (wid < 4) {
#pragma unroll
                for (int kt = 0; kt < 6; kt++) {
                    int kc = kt * 16 + 2 * tq4;
                    unsigned a0 = *(const unsigned*)&sA[g][kc];
                    unsigned a1 = *(const unsigned*)&sA[g + 8][kc];
                    unsigned a2 = *(const unsigned*)&sA[g][kc + 8];
                    unsigned a3 = *(const unsigned*)&sA[g + 8][kc + 8];
                    unsigned b0 = *(const unsigned*)&sBBh[j][kc];
                    unsigned b1 = *(const unsigned*)&sBBh[j][kc + 8];
                    mma16816(c0, c1, cc2, c3, a0, a1, a2, a3, b0, b1);
                }
            } else {
#pragma unroll
                for (int kt = 2; kt < 6; kt++) {
                    int kc = kt * 16 + 2 * tq4;
                    unsigned a0 = *(const unsigned*)&sA[g][kc];
                    unsigned a1 = *(const unsigned*)&sA[g + 8][kc];
                    unsigned a2 = *(const unsigned*)&sA[g][kc + 8];
                    unsigned a3 = *(const unsigned*)&sA[g + 8][kc + 8];
                    unsigned b0 = *(const unsigned*)&sBBl[j][kc];
                    unsigned b1 = *(const unsigned*)&sBBl[j][kc + 8];
                    mma16816(c0, c1, cc2, c3, a0, a1, a2, a3, b0, b1);
                }
            }
            int jc = ((wid < 4) ? 0 : 32) + 8 * wsub + 2 * tq4;
            *(float2*)&sZT[g][jc]     = make_float2(c0, c1);
            *(float2*)&sZT[g + 8][jc] = make_float2(cc2, c3);
            __syncthreads();

            // epilogue: hn = Z*h + (1-Z)*tanh(hi+lo+bias); stage hn for fc
            float hn[2];
#pragma unroll
            for (int q = 0; q < 2; q++) {
                int it = tid + q * 256;
                int nn = it >> 5, c = it & 31;
                int gn = n0 + nn;
                float ct = sZT[nn][c] + sZT[nn][32 + c] + s_bh[c];
                float z = g_Z[gn * CH + c];
                float h = g_h[gn * CH + c];
                float v = z * h + (1.f - z) * tanhf(ct);
                hn[q] = v;
                g_h[gn * CH + c] = v;
                g_h16[gn * CH + c] = __float2half(v);
            }
            __syncthreads();
#pragma unroll
            for (int q = 0; q < 2; q++) {
                int it = tid + q * 256;
                sZT[it >> 5][it & 31] = hn[q];
            }
            __syncthreads();
            if (tid < 128) {
                int nn = tid >> 3, jj = tid & 7;
                float acc = s_fcb[jj];
#pragma unroll
                for (int c = 0; c < CH; c++) acc += sZT[nn][c] * s_fcw[c * COUTC + jj];
                out[((size_t)t * NN + n0 + nn) * COUTC + jj] = acc;
            }
            __syncthreads();
        }

        // ---- grid barrier (h published for next step) ----
        gen++;
        __syncthreads();
        if (tid == 0) {
            __threadfence();
            if (atomicAdd(&g_cnt, 1) == NB - 1) {
                g_cnt = 0;
                __threadfence();
                g_release = gen;
            } else {
                while (g_release < gen) { }
            }
        }
        __syncthreads();
    }
}

// ---------------- launch ----------------
extern "C" void kernel_launch(void* const* d_in, const int* in_sizes, int n_in,
                              void* d_out, int out_size) {
    const float* X   = (const float*)d_in[0];
    const void*  ei  = d_in[1];
    const float* Wxz = (const float*)d_in[2];
    const float* bxz = (const float*)d_in[3];
    const float* Whz = (const float*)d_in[4];
    const float* bhz = (const float*)d_in[5];
    const float* Wxr = (const float*)d_in[6];
    const float* bxr = (const float*)d_in[7];
    const float* Whr = (const float*)d_in[8];
    const float* bhr = (const float*)d_in[9];
    const float* Wxh = (const float*)d_in[10];
    const float* bxh = (const float*)d_in[11];
    const float* Whh = (const float*)d_in[12];
    const float* bhh = (const float*)d_in[13];
    const float* fcw = (const float*)d_in[14];
    const float* fcb = (const float*)d_in[15];
    float* out = (float*)d_out;

    int E = in_sizes[1] / 2;

    // preprocess: count(0), scan(1), fill(2) -> k_gru is launch idx 3 (ncu!)
    k_count<<<(E + 255) / 256, 256>>>(ei, X, E);
    k_scan<<<1, 1024>>>();
    k_fill<<<(E + 255) / 256, 256>>>(ei, E);

    // persistent: AX prologue + all 128 recurrence steps in ONE launch
    k_gru<<<NB, 256>>>(Wxz, bxz, Whz, bhz, Wxr, bxr, Whr, bhr,
                       Wxh, bxh, Whh, bhh, fcw, fcb, out);
}